// round 9
// baseline (speedup 1.0000x reference)
#include <cuda_runtime.h>
#include <cuda_bf16.h>

// Problem constants
#define Bb 8
#define Cc 2048
#define Ll 3
#define Vv 512
#define Hh 256
#define HEADS 8
#define HD 32
#define ITERS 8
#define TWOH 512
#define NTOK (Bb*Cc)      // 16384
#define NVAR (Bb*Vv)      // 4096

// ---------------- scratch (static device globals; no allocation) ----------------
__device__ float g_mean[NTOK*Hh];
__device__ float g_x1[NTOK*TWOH];
__device__ float g_base[NTOK*Hh];
__device__ float g_Kb[NTOK*Hh];
__device__ float g_Vb[NTOK*Hh];
__device__ unsigned g_Kh[NTOK*128];   // bf16-hi plane of Kb, dim-pair packed
__device__ unsigned g_Kl[NTOK*128];   // bf16-lo plane
__device__ unsigned g_VhT[64*32*1024]; // V hi, transposed: [(b,h)][dim][clause-pair]
__device__ unsigned g_VlT[64*32*1024];
__device__ float g_var[NVAR*Hh];
__device__ float g_attno[NVAR*Hh];
__device__ float g_vs[NVAR*Hh];
__device__ float g_h1[NVAR*Hh];
__device__ int   g_assign[NVAR];
__device__ int   g_sel[Bb];
__device__ int   g_conflict;
__device__ int   g_done;

__device__ __forceinline__ float gelu_f(float x) {
    return 0.5f * x * (1.0f + erff(x * 0.70710678118654752440f));
}

// ---------------- bf16 split helpers ----------------
__device__ __forceinline__ void sp2(float x, float y, unsigned &uh, unsigned &ul) {
    float xh = __bfloat162float(__float2bfloat16_rn(x));
    float yh = __bfloat162float(__float2bfloat16_rn(y));
    float xl = x - xh, yl = y - yh;
    asm("cvt.rn.bf16x2.f32 %0, %1, %2;" : "=r"(uh) : "f"(yh), "f"(xh));
    asm("cvt.rn.bf16x2.f32 %0, %1, %2;" : "=r"(ul) : "f"(yl), "f"(xl));
}

__device__ __forceinline__ void mma_bf16(float &c0, float &c1, float &c2, float &c3,
                                         unsigned a0, unsigned a1, unsigned a2, unsigned a3,
                                         unsigned b0, unsigned b1) {
    asm volatile("mma.sync.aligned.m16n8k16.row.col.f32.bf16.bf16.f32 "
                 "{%0,%1,%2,%3}, {%4,%5,%6,%7}, {%8,%9}, {%0,%1,%2,%3};"
                 : "+f"(c0), "+f"(c1), "+f"(c2), "+f"(c3)
                 : "r"(a0), "r"(a1), "r"(a2), "r"(a3), "r"(b0), "r"(b1));
}

// ---------------- init ----------------
__global__ void k_init(float* var, int* assign, int* done, int* conflict) {
    int i = blockIdx.x * 256 + threadIdx.x;
    if (i < NVAR*Hh) var[i] = 0.f;
    if (i < NVAR) assign[i] = 2;
    if (i == 0) { *done = 0; *conflict = 0; }
}

// ---------------- split K into packed bf16 planes ----------------
__global__ void k_splitK(const float* __restrict__ Kb, unsigned* __restrict__ Kh,
                         unsigned* __restrict__ Kl) {
    int i = blockIdx.x * 256 + threadIdx.x;    // NTOK*128
    unsigned uh, ul;
    sp2(Kb[2*i], Kb[2*i+1], uh, ul);
    Kh[i] = uh; Kl[i] = ul;
}

// ---------------- split + transpose V: [(b,h)][dim 32][clause-pair 1024] ----------------
__global__ void k_splitVT(const float* __restrict__ Vb, unsigned* __restrict__ VhT,
                          unsigned* __restrict__ VlT) {
    int bh = blockIdx.x;          // 0..63
    int b = bh >> 3, h = bh & 7;
    int t = threadIdx.x;          // 256
    __shared__ float tile[64][33];
    for (int cc = 0; cc < Cc; cc += 64) {
        __syncthreads();
        #pragma unroll
        for (int rep = 0; rep < 8; rep++) {
            int idx = rep*256 + t;
            int cl = idx >> 5, d = idx & 31;
            tile[cl][d] = Vb[(long)(b*Cc + cc + cl)*Hh + h*32 + d];
        }
        __syncthreads();
        int d = t >> 3, j = t & 7;
        unsigned oh[4], ol[4];
        #pragma unroll
        for (int qq = 0; qq < 4; qq++) {
            int cp = j*4 + qq;
            sp2(tile[2*cp][d], tile[2*cp+1][d], oh[qq], ol[qq]);
        }
        long obase = ((long)(bh*32 + d) << 10) + (cc >> 1) + j*4;
        *(uint4*)(VhT + obase) = make_uint4(oh[0],oh[1],oh[2],oh[3]);
        *(uint4*)(VlT + obase) = make_uint4(ol[0],ol[1],ol[2],ol[3]);
    }
}

// ---------------- literal gather + mean over L ----------------
__global__ void k_mean(const int* __restrict__ formula, const float* __restrict__ lit_emb,
                       float* __restrict__ out) {
    int token = blockIdx.x;
    int d = threadIdx.x;
    int f0 = formula[token*3+0], f1 = formula[token*3+1], f2 = formula[token*3+2];
    float s = lit_emb[f0*Hh+d] + lit_emb[f1*Hh+d] + lit_emb[f2*Hh+d];
    out[(long)token*Hh + d] = s * (1.0f/3.0f);
}

// ---------------- LayerNorm (rows of 512) + gelu, in-place ----------------
__global__ void k_ln_gelu(float* __restrict__ x, const float* __restrict__ g,
                          const float* __restrict__ beta) {
    int row = blockIdx.x; int t = threadIdx.x;
    __shared__ float red[256];
    float a = x[(long)row*TWOH + t];
    float b_ = x[(long)row*TWOH + t + 256];
    red[t] = a + b_;
    __syncthreads();
    for (int s = 128; s; s >>= 1) { if (t < s) red[t] += red[t+s]; __syncthreads(); }
    float mean = red[0] * (1.0f/512.0f);
    __syncthreads();
    float da = a - mean, db = b_ - mean;
    red[t] = da*da + db*db;
    __syncthreads();
    for (int s = 128; s; s >>= 1) { if (t < s) red[t] += red[t+s]; __syncthreads(); }
    float var = red[0] * (1.0f/512.0f);
    float rstd = rsqrtf(var + 1e-5f);
    float ya = da * rstd * g[t]     + beta[t];
    float yb = db * rstd * g[t+256] + beta[t+256];
    x[(long)row*TWOH + t]       = gelu_f(ya);
    x[(long)row*TWOH + t + 256] = gelu_f(yb);
}

// ---------------- tensor-core 3-pass bf16 GEMM ----------------
__global__ void __launch_bounds__(128) k_gemm_tc(
        const float* __restrict__ A, const float* __restrict__ W,
        const float* __restrict__ bias, float* __restrict__ C,
        float* __restrict__ C2,
        int M, int N, int K, int act, const int* done) {
    if (done && *done) return;
    __shared__ unsigned Ash[64][20], Asl[64][20];
    __shared__ unsigned Wsh[64][20], Wsl[64][20];
    int t = threadIdx.x, lane = t & 31, w = t >> 5;
    int gid = lane >> 2, tid = lane & 3;
    int m0 = blockIdx.y * 64, n0 = blockIdx.x * 64;
    float acc[8][4] = {};
    for (int k0 = 0; k0 < K; k0 += 32) {
        __syncthreads();
        #pragma unroll
        for (int rep = 0; rep < 4; rep++) {
            int idx = t + rep*128;
            int r = idx >> 3, c4 = (idx & 7) << 2;
            float4 av = *(const float4*)(A + (long)(m0+r)*K + k0 + c4);
            unsigned h0,l0,h1,l1;
            sp2(av.x, av.y, h0, l0); sp2(av.z, av.w, h1, l1);
            Ash[r][(c4>>1)] = h0; Ash[r][(c4>>1)+1] = h1;
            Asl[r][(c4>>1)] = l0; Asl[r][(c4>>1)+1] = l1;
            float4 wv = *(const float4*)(W + (long)(n0+r)*K + k0 + c4);
            sp2(wv.x, wv.y, h0, l0); sp2(wv.z, wv.w, h1, l1);
            Wsh[r][(c4>>1)] = h0; Wsh[r][(c4>>1)+1] = h1;
            Wsl[r][(c4>>1)] = l0; Wsl[r][(c4>>1)+1] = l1;
        }
        __syncthreads();
        #pragma unroll
        for (int kt = 0; kt < 2; kt++) {
            int ra = w*16 + gid, ku = kt*8 + tid;
            unsigned ah0 = Ash[ra  ][ku],  ah1 = Ash[ra+8][ku];
            unsigned ah2 = Ash[ra  ][ku+4], ah3 = Ash[ra+8][ku+4];
            unsigned al0 = Asl[ra  ][ku],  al1 = Asl[ra+8][ku];
            unsigned al2 = Asl[ra  ][ku+4], al3 = Asl[ra+8][ku+4];
            #pragma unroll
            for (int nt = 0; nt < 8; nt++) {
                int rb = nt*8 + gid;
                unsigned bh0 = Wsh[rb][ku], bh1 = Wsh[rb][ku+4];
                unsigned bl0 = Wsl[rb][ku], bl1 = Wsl[rb][ku+4];
                mma_bf16(acc[nt][0],acc[nt][1],acc[nt][2],acc[nt][3], ah0,ah1,ah2,ah3, bh0,bh1);
                mma_bf16(acc[nt][0],acc[nt][1],acc[nt][2],acc[nt][3], ah0,ah1,ah2,ah3, bl0,bl1);
                mma_bf16(acc[nt][0],acc[nt][1],acc[nt][2],acc[nt][3], al0,al1,al2,al3, bh0,bh1);
            }
        }
    }
    int r = m0 + w*16 + gid;
    #pragma unroll
    for (int nt = 0; nt < 8; nt++) {
        int c = n0 + nt*8 + 2*tid;
        float b0v = bias ? bias[c] : 0.0f;
        float b1v = bias ? bias[c+1] : 0.0f;
        float v0 = acc[nt][0] + b0v, v1 = acc[nt][1] + b1v;
        float v2 = acc[nt][2] + b0v, v3 = acc[nt][3] + b1v;
        if (act) { v0 = gelu_f(v0); v1 = gelu_f(v1); v2 = gelu_f(v2); v3 = gelu_f(v3); }
        *(float2*)(C + (long)r*N + c)     = make_float2(v0, v1);
        *(float2*)(C + (long)(r+8)*N + c) = make_float2(v2, v3);
        if (C2) {
            *(float2*)(C2 + (long)r*N + c)     = make_float2(v0, v1);
            *(float2*)(C2 + (long)(r+8)*N + c) = make_float2(v2, v3);
        }
    }
}

// ---------------- flash attention with fused Q-projection ----------------
// grid: B*HEADS*(V/64) = 512 blocks, 128 threads (4 warps x 16 q-rows).
#define BQ 64
#define BC 64
__global__ void __launch_bounds__(128) k_attn(
        const float* __restrict__ var, const float* __restrict__ attn_in_w,
        const unsigned* __restrict__ Kh, const unsigned* __restrict__ Kl,
        const unsigned* __restrict__ VhT, const unsigned* __restrict__ VlT,
        const int* __restrict__ formula, const int* __restrict__ assign,
        const float* __restrict__ attn_in_b, float* __restrict__ out,
        const int* __restrict__ done) {
    if (*done) return;
    int bid = blockIdx.x;
    int qt = bid & 7;
    int h  = (bid >> 3) & 7;
    int b  = bid >> 6;
    int t = threadIdx.x, lane = t & 31, w = t >> 5;
    int gid = lane >> 2, tid = lane & 3;

    __shared__ unsigned Ksh[BC][20], Ksl[BC][20];     // K planes / var planes (prologue)
    __shared__ unsigned Vsh[HD][36], Vsl[HD][36];     // V planes / Wq planes (prologue)
    __shared__ float    scs[BC];

    int row0 = qt * BQ;

    // ---- fused Q projection: qacc = var[rows] @ Wq[h]^T (3-pass bf16) ----
    float qacc[4][4] = {};
    for (int k0 = 0; k0 < Hh; k0 += 32) {
        __syncthreads();
        #pragma unroll
        for (int rep = 0; rep < 4; rep++) {
            int idx = t + rep*128;
            int r = idx >> 3, c4 = (idx & 7) << 2;
            float4 av = *(const float4*)(var + ((long)(b*Vv + row0 + r) << 8) + k0 + c4);
            unsigned h0,l0,h1,l1;
            sp2(av.x, av.y, h0, l0); sp2(av.z, av.w, h1, l1);
            Ksh[r][(c4>>1)] = h0; Ksh[r][(c4>>1)+1] = h1;
            Ksl[r][(c4>>1)] = l0; Ksl[r][(c4>>1)+1] = l1;
        }
        #pragma unroll
        for (int rep = 0; rep < 2; rep++) {
            int idx = t + rep*128;
            int r = idx >> 3, c4 = (idx & 7) << 2;       // r 0..31
            float4 wv = *(const float4*)(attn_in_w + (long)(h*HD + r)*Hh + k0 + c4);
            unsigned h0,l0,h1,l1;
            sp2(wv.x, wv.y, h0, l0); sp2(wv.z, wv.w, h1, l1);
            Vsh[r][(c4>>1)] = h0; Vsh[r][(c4>>1)+1] = h1;
            Vsl[r][(c4>>1)] = l0; Vsl[r][(c4>>1)+1] = l1;
        }
        __syncthreads();
        #pragma unroll
        for (int kt = 0; kt < 2; kt++) {
            int ra = w*16 + gid, ku = kt*8 + tid;
            unsigned ah0 = Ksh[ra  ][ku],  ah1 = Ksh[ra+8][ku];
            unsigned ah2 = Ksh[ra  ][ku+4], ah3 = Ksh[ra+8][ku+4];
            unsigned al0 = Ksl[ra  ][ku],  al1 = Ksl[ra+8][ku];
            unsigned al2 = Ksl[ra  ][ku+4], al3 = Ksl[ra+8][ku+4];
            #pragma unroll
            for (int nt = 0; nt < 4; nt++) {
                int rb = nt*8 + gid;
                unsigned bh0 = Vsh[rb][ku], bh1 = Vsh[rb][ku+4];
                unsigned bl0 = Vsl[rb][ku], bl1 = Vsl[rb][ku+4];
                mma_bf16(qacc[nt][0],qacc[nt][1],qacc[nt][2],qacc[nt][3], ah0,ah1,ah2,ah3, bh0,bh1);
                mma_bf16(qacc[nt][0],qacc[nt][1],qacc[nt][2],qacc[nt][3], ah0,ah1,ah2,ah3, bl0,bl1);
                mma_bf16(qacc[nt][0],qacc[nt][1],qacc[nt][2],qacc[nt][3], al0,al1,al2,al3, bh0,bh1);
            }
        }
    }
    // add q-bias; compute qb = q . bk via quad reduce (fp32)
    const float* bqp = attn_in_b + h*HD;
    const float* bkp = attn_in_b + Hh + h*HD;
    float p0 = 0.f, p1 = 0.f;
    #pragma unroll
    for (int nt = 0; nt < 4; nt++) {
        float b0 = bqp[nt*8 + 2*tid], b1v = bqp[nt*8 + 2*tid + 1];
        qacc[nt][0] += b0; qacc[nt][1] += b1v;
        qacc[nt][2] += b0; qacc[nt][3] += b1v;
        float k0v = bkp[nt*8 + 2*tid], k1v = bkp[nt*8 + 2*tid + 1];
        p0 += qacc[nt][0]*k0v + qacc[nt][1]*k1v;
        p1 += qacc[nt][2]*k0v + qacc[nt][3]*k1v;
    }
    p0 += __shfl_xor_sync(0xffffffffu, p0, 1);
    p0 += __shfl_xor_sync(0xffffffffu, p0, 2);
    p1 += __shfl_xor_sync(0xffffffffu, p1, 1);
    p1 += __shfl_xor_sync(0xffffffffu, p1, 2);
    float qb0 = p0, qb1 = p1;

    // Q fragments (C-frag of q-gemm == A-frag of QK)
    unsigned qh[2][4], ql[2][4];
    #pragma unroll
    for (int kt = 0; kt < 2; kt++) {
        sp2(qacc[2*kt  ][0], qacc[2*kt  ][1], qh[kt][0], ql[kt][0]);
        sp2(qacc[2*kt  ][2], qacc[2*kt  ][3], qh[kt][1], ql[kt][1]);
        sp2(qacc[2*kt+1][0], qacc[2*kt+1][1], qh[kt][2], ql[kt][2]);
        sp2(qacc[2*kt+1][2], qacc[2*kt+1][3], qh[kt][3], ql[kt][3]);
    }

    float m0 = -1e30f, m1 = -1e30f, s0a = 0.f, s1a = 0.f;
    float o_[4][4] = {};
    const float inv = 0.17677669529663688110f;   // 1/sqrt(32)
    long vbase = ((long)((b*8 + h)*HD) << 10);

    for (int c0 = 0; c0 < Cc; c0 += BC) {
        __syncthreads();
        // fused clause-scale
        if (t < BC) {
            int cg = b*Cc + c0 + t;
            int f0 = formula[cg*3+0], f1 = formula[cg*3+1], f2 = formula[cg*3+2];
            int a0 = assign[b*Vv + (f0>>1)];
            int a1 = assign[b*Vv + (f1>>1)];
            int a2 = assign[b*Vv + (f2>>1)];
            bool sat = (a0 == (f0&1)) || (a1 == (f1&1)) || (a2 == (f2&1));
            scs[t] = sat ? 0.1f : 1.0f;
        }
        #pragma unroll
        for (int rep = 0; rep < 2; rep++) {
            int idx4 = t + rep*128;
            int c = idx4 >> 2, u4 = (idx4 & 3) << 2;
            long gix = ((long)(b*Cc + c0 + c) << 7) + (h << 4) + u4;
            *(uint4*)(&Ksh[c][u4]) = *(const uint4*)(Kh + gix);
            *(uint4*)(&Ksl[c][u4]) = *(const uint4*)(Kl + gix);
        }
        #pragma unroll
        for (int rep = 0; rep < 2; rep++) {
            int idx4 = t + rep*128;
            int d = idx4 >> 3, j4 = (idx4 & 7) << 2;
            long gix = vbase + ((long)d << 10) + (c0 >> 1) + j4;
            *(uint4*)(&Vsh[d][j4]) = *(const uint4*)(VhT + gix);
            *(uint4*)(&Vsl[d][j4]) = *(const uint4*)(VlT + gix);
        }
        __syncthreads();

        float sc_[8][4];
        #pragma unroll
        for (int nt = 0; nt < 8; nt++) {
            float a0 = 0.f, a1 = 0.f, a2 = 0.f, a3 = 0.f;
            #pragma unroll
            for (int kt = 0; kt < 2; kt++) {
                int cn = nt*8 + gid, ku = kt*8 + tid;
                unsigned bh0 = Ksh[cn][ku], bh1 = Ksh[cn][ku+4];
                unsigned bl0 = Ksl[cn][ku], bl1 = Ksl[cn][ku+4];
                mma_bf16(a0,a1,a2,a3, qh[kt][0],qh[kt][1],qh[kt][2],qh[kt][3], bh0,bh1);
                mma_bf16(a0,a1,a2,a3, qh[kt][0],qh[kt][1],qh[kt][2],qh[kt][3], bl0,bl1);
                mma_bf16(a0,a1,a2,a3, ql[kt][0],ql[kt][1],ql[kt][2],ql[kt][3], bh0,bh1);
            }
            sc_[nt][0]=a0; sc_[nt][1]=a1; sc_[nt][2]=a2; sc_[nt][3]=a3;
        }

        float rm0 = -1e30f, rm1 = -1e30f;
        #pragma unroll
        for (int nt = 0; nt < 8; nt++) {
            float scA = scs[nt*8 + 2*tid];
            float scB = scs[nt*8 + 2*tid + 1];
            sc_[nt][0] = fmaf(sc_[nt][0], scA, qb0) * inv;
            sc_[nt][1] = fmaf(sc_[nt][1], scB, qb0) * inv;
            sc_[nt][2] = fmaf(sc_[nt][2], scA, qb1) * inv;
            sc_[nt][3] = fmaf(sc_[nt][3], scB, qb1) * inv;
            rm0 = fmaxf(rm0, fmaxf(sc_[nt][0], sc_[nt][1]));
            rm1 = fmaxf(rm1, fmaxf(sc_[nt][2], sc_[nt][3]));
        }
        rm0 = fmaxf(rm0, __shfl_xor_sync(0xffffffffu, rm0, 1));
        rm0 = fmaxf(rm0, __shfl_xor_sync(0xffffffffu, rm0, 2));
        rm1 = fmaxf(rm1, __shfl_xor_sync(0xffffffffu, rm1, 1));
        rm1 = fmaxf(rm1, __shfl_xor_sync(0xffffffffu, rm1, 2));
        float mn0 = fmaxf(m0, rm0), mn1 = fmaxf(m1, rm1);
        float corr0 = __expf(m0 - mn0), corr1 = __expf(m1 - mn1);
        float ps0 = 0.f, ps1 = 0.f;
        #pragma unroll
        for (int nt = 0; nt < 8; nt++) {
            sc_[nt][0] = __expf(sc_[nt][0] - mn0);
            sc_[nt][1] = __expf(sc_[nt][1] - mn0);
            sc_[nt][2] = __expf(sc_[nt][2] - mn1);
            sc_[nt][3] = __expf(sc_[nt][3] - mn1);
            ps0 += sc_[nt][0] + sc_[nt][1];
            ps1 += sc_[nt][2] + sc_[nt][3];
        }
        ps0 += __shfl_xor_sync(0xffffffffu, ps0, 1);
        ps0 += __shfl_xor_sync(0xffffffffu, ps0, 2);
        ps1 += __shfl_xor_sync(0xffffffffu, ps1, 1);
        ps1 += __shfl_xor_sync(0xffffffffu, ps1, 2);
        s0a = s0a*corr0 + ps0;
        s1a = s1a*corr1 + ps1;
        m0 = mn0; m1 = mn1;

        #pragma unroll
        for (int nt2 = 0; nt2 < 4; nt2++) {
            o_[nt2][0] *= corr0; o_[nt2][1] *= corr0;
            o_[nt2][2] *= corr1; o_[nt2][3] *= corr1;
        }

        #pragma unroll
        for (int kt = 0; kt < 4; kt++) {
            int cA = kt*16 + 2*tid;
            float sA = scs[cA], sB = scs[cA+1], sC = scs[cA+8], sD = scs[cA+9];
            unsigned ah0, al0, ah1, al1, ah2, al2, ah3, al3;
            sp2(sc_[2*kt  ][0]*sA, sc_[2*kt  ][1]*sB, ah0, al0);
            sp2(sc_[2*kt  ][2]*sA, sc_[2*kt  ][3]*sB, ah1, al1);
            sp2(sc_[2*kt+1][0]*sC, sc_[2*kt+1][1]*sD, ah2, al2);
            sp2(sc_[2*kt+1][2]*sC, sc_[2*kt+1][3]*sD, ah3, al3);
            #pragma unroll
            for (int nt2 = 0; nt2 < 4; nt2++) {
                int d = nt2*8 + gid, ku = kt*8 + tid;
                unsigned bh0 = Vsh[d][ku], bh1 = Vsh[d][ku+4];
                unsigned bl0 = Vsl[d][ku], bl1 = Vsl[d][ku+4];
                mma_bf16(o_[nt2][0],o_[nt2][1],o_[nt2][2],o_[nt2][3], ah0,ah1,ah2,ah3, bh0,bh1);
                mma_bf16(o_[nt2][0],o_[nt2][1],o_[nt2][2],o_[nt2][3], ah0,ah1,ah2,ah3, bl0,bl1);
                mma_bf16(o_[nt2][0],o_[nt2][1],o_[nt2][2],o_[nt2][3], al0,al1,al2,al3, bh0,bh1);
            }
        }
    }

    const float* bvp = attn_in_b + 2*Hh + h*HD;
    float is0 = 1.0f / s0a, is1 = 1.0f / s1a;
    int r0 = row0 + w*16 + gid;
    #pragma unroll
    for (int nt2 = 0; nt2 < 4; nt2++) {
        int d = nt2*8 + 2*tid;
        float2 bvv = *(const float2*)(bvp + d);
        float2 w0 = make_float2(o_[nt2][0]*is0 + bvv.x, o_[nt2][1]*is0 + bvv.y);
        float2 w1v = make_float2(o_[nt2][2]*is1 + bvv.x, o_[nt2][3]*is1 + bvv.y);
        *(float2*)(out + ((long)(b*Vv + r0)     << 8) + (h << 5) + d) = w0;
        *(float2*)(out + ((long)(b*Vv + r0 + 8) << 8) + (h << 5) + d) = w1v;
    }
}

// ---------------- fused decide: scores + argmax + ap head + assign + conflict ----------------
// grid: Bb blocks, 256 threads
__global__ void k_decide(const float* __restrict__ h1, const float* __restrict__ vw2,
                         const float* __restrict__ vb2,
                         const float* __restrict__ vs, int* __restrict__ assign,
                         const float* __restrict__ w1, const float* __restrict__ b1,
                         const float* __restrict__ w2, const float* __restrict__ b2,
                         const int* __restrict__ formula,
                         int* __restrict__ sel_out, const int* __restrict__ done,
                         int* __restrict__ conflict) {
    int b = blockIdx.x, t = threadIdx.x;
    if (*done) return;
    __shared__ float sc[512];
    __shared__ float sv[256];
    __shared__ int   si[256];
    __shared__ float vsel[256];
    __shared__ float hbuf[256];
    __shared__ float r0s[256];
    __shared__ float r1s[256];
    int w = t >> 5, lane = t & 31;
    // scores: 512 rows, warp-per-row round robin
    for (int r = w; r < Vv; r += 8) {
        const float* hr = h1 + ((long)(b*Vv + r)) * Hh;
        float acc = 0.f;
        #pragma unroll
        for (int i = 0; i < 8; i++) acc = fmaf(hr[lane + 32*i], vw2[lane + 32*i], acc);
        #pragma unroll
        for (int o = 16; o; o >>= 1) acc += __shfl_xor_sync(0xffffffffu, acc, o);
        if (lane == 0) {
            float s = acc + vb2[0];
            if (assign[b*Vv + r] != 2) s += -1000000000.0f;
            sc[r] = s;
        }
    }
    __syncthreads();
    // argmax (first index wins)
    float v1 = sc[t], v2 = sc[t + 256];
    float bvv; int bi;
    if (v2 > v1) { bvv = v2; bi = t + 256; } else { bvv = v1; bi = t; }
    sv[t] = bvv; si[t] = bi;
    __syncthreads();
    for (int s = 128; s; s >>= 1) {
        if (t < s) {
            if (sv[t+s] > sv[t] || (sv[t+s] == sv[t] && si[t+s] < si[t])) {
                sv[t] = sv[t+s]; si[t] = si[t+s];
            }
        }
        __syncthreads();
    }
    int sel = si[0];
    vsel[t] = vs[((long)(b*Vv + sel)) * Hh + t];
    __syncthreads();
    for (int oo = 0; oo < 32; oo++) {
        int o = w*32 + oo;
        float acc = 0.f;
        #pragma unroll
        for (int kk = 0; kk < 8; kk++)
            acc = fmaf(w1[o*Hh + lane + 32*kk], vsel[lane + 32*kk], acc);
        #pragma unroll
        for (int off = 16; off; off >>= 1) acc += __shfl_xor_sync(0xffffffffu, acc, off);
        if (lane == 0) hbuf[o] = gelu_f(acc + b1[o]);
    }
    __syncthreads();
    float hv = hbuf[t];
    r0s[t] = hv * w2[t];
    r1s[t] = hv * w2[Hh + t];
    __syncthreads();
    for (int s = 128; s; s >>= 1) {
        if (t < s) { r0s[t] += r0s[t+s]; r1s[t] += r1s[t+s]; }
        __syncthreads();
    }
    if (t == 0) {
        float l0 = r0s[0] + b2[0], l1 = r1s[0] + b2[1];
        assign[b*Vv + sel] = (l1 > l0) ? 1 : 0;
        sel_out[b] = sel;
    }
    __syncthreads();
    // conflict detection on own batch (post-update)
    int myconf = 0;
    for (int i = t; i < Cc; i += 256) {
        int cg = b*Cc + i;
        int f0 = formula[cg*3+0], f1 = formula[cg*3+1], f2 = formula[cg*3+2];
        int a0 = assign[b*Vv + (f0>>1)];
        int a1 = assign[b*Vv + (f1>>1)];
        int a2 = assign[b*Vv + (f2>>1)];
        bool sat = (a0 == (f0&1)) || (a1 == (f1&1)) || (a2 == (f2&1));
        bool allass = (a0 != 2) && (a1 != 2) && (a2 != 2);
        if (allass && !sat) myconf = 1;
    }
    if (__syncthreads_or(myconf)) {
        if (t == 0) atomicOr(conflict, 1);
    }
}

// ---------------- rollback + done update (also resets conflict for next iter) ----------------
__global__ void k_finalize(int* __restrict__ assign, const int* __restrict__ sel,
                           int* __restrict__ done, int* __restrict__ conflict) {
    __shared__ int red[256];
    __shared__ int sconf;
    int t = threadIdx.x;
    if (*done) return;
    if (t == 0) { sconf = *conflict; *conflict = 0; }
    __syncthreads();
    int conf = sconf;
    if (conf && t < Bb) assign[t*Vv + sel[t]] = 2;
    __syncthreads();
    int ok = 1;
    for (int i = t; i < NVAR; i += 256) ok &= (assign[i] != 2) ? 1 : 0;
    red[t] = ok;
    __syncthreads();
    for (int s = 128; s; s >>= 1) { if (t < s) red[t] &= red[t+s]; __syncthreads(); }
    if (t == 0 && red[0] && !conf) *done = 1;
}

// ---------------- final sat-probability head ----------------
__global__ void k_satout(const float* __restrict__ var,
                         const float* __restrict__ w1, const float* __restrict__ b1,
                         const float* __restrict__ w2, const float* __restrict__ b2,
                         float* __restrict__ out) {
    int b = blockIdx.x, t = threadIdx.x;
    __shared__ float msh[256];
    __shared__ float hbuf[256];
    __shared__ float red[256];
    float ssum_ = 0.f;
    for (int v = 0; v < Vv; v++) ssum_ += var[((long)(b*Vv + v)) * Hh + t];
    msh[t] = ssum_ * (1.0f/512.0f);
    __syncthreads();
    int w = t >> 5, lane = t & 31;
    for (int oo = 0; oo < 32; oo++) {
        int o = w*32 + oo;
        float acc = 0.f;
        #pragma unroll
        for (int kk = 0; kk < 8; kk++)
            acc = fmaf(w1[o*Hh + lane + 32*kk], msh[lane + 32*kk], acc);
        #pragma unroll
        for (int off = 16; off; off >>= 1) acc += __shfl_xor_sync(0xffffffffu, acc, off);
        if (lane == 0) hbuf[o] = gelu_f(acc + b1[o]);
    }
    __syncthreads();
    red[t] = hbuf[t] * w2[t];
    __syncthreads();
    for (int s = 128; s; s >>= 1) { if (t < s) red[t] += red[t+s]; __syncthreads(); }
    if (t == 0) {
        float l = red[0] + b2[0];
        out[b] = 1.0f / (1.0f + expf(-l));
    }
}

__global__ void k_assignout(const int* __restrict__ assign, float* __restrict__ out) {
    int i = blockIdx.x * 256 + threadIdx.x;
    if (i < NVAR) out[Bb + i] = (float)assign[i];
}

// ---------------- host launch ----------------
extern "C" void kernel_launch(void* const* d_in, const int* in_sizes, int n_in,
                              void* d_out, int out_size) {
    const int*   formula    = (const int*)  d_in[0];
    const float* lit_emb    = (const float*)d_in[1];
    const float* ce_w1      = (const float*)d_in[2];
    const float* ce_b1      = (const float*)d_in[3];
    const float* ce_g       = (const float*)d_in[4];
    const float* ce_beta    = (const float*)d_in[5];
    const float* ce_w2      = (const float*)d_in[6];
    const float* ce_b2      = (const float*)d_in[7];
    const float* attn_in_w  = (const float*)d_in[8];
    const float* attn_in_b  = (const float*)d_in[9];
    const float* attn_out_w = (const float*)d_in[10];
    const float* attn_out_b = (const float*)d_in[11];
    const float* vs_w1      = (const float*)d_in[12];
    const float* vs_b1      = (const float*)d_in[13];
    const float* vs_w2      = (const float*)d_in[14];
    const float* vs_b2      = (const float*)d_in[15];
    const float* ap_w1      = (const float*)d_in[16];
    const float* ap_b1      = (const float*)d_in[17];
    const float* ap_w2      = (const float*)d_in[18];
    const float* ap_b2      = (const float*)d_in[19];
    const float* sp_w1      = (const float*)d_in[20];
    const float* sp_b1      = (const float*)d_in[21];
    const float* sp_w2      = (const float*)d_in[22];
    const float* sp_b2      = (const float*)d_in[23];
    float* out = (float*)d_out;

    float *p_mean, *p_x1, *p_base, *p_Kb, *p_Vb, *p_var, *p_attno, *p_vs, *p_h1;
    unsigned *p_Kh, *p_Kl, *p_VhT, *p_VlT;
    int *p_assign, *p_sel, *p_conf, *p_done;
    cudaGetSymbolAddress((void**)&p_mean,  g_mean);
    cudaGetSymbolAddress((void**)&p_x1,    g_x1);
    cudaGetSymbolAddress((void**)&p_base,  g_base);
    cudaGetSymbolAddress((void**)&p_Kb,    g_Kb);
    cudaGetSymbolAddress((void**)&p_Vb,    g_Vb);
    cudaGetSymbolAddress((void**)&p_Kh,    g_Kh);
    cudaGetSymbolAddress((void**)&p_Kl,    g_Kl);
    cudaGetSymbolAddress((void**)&p_VhT,   g_VhT);
    cudaGetSymbolAddress((void**)&p_VlT,   g_VlT);
    cudaGetSymbolAddress((void**)&p_var,   g_var);
    cudaGetSymbolAddress((void**)&p_attno, g_attno);
    cudaGetSymbolAddress((void**)&p_vs,    g_vs);
    cudaGetSymbolAddress((void**)&p_h1,    g_h1);
    cudaGetSymbolAddress((void**)&p_assign,g_assign);
    cudaGetSymbolAddress((void**)&p_sel,   g_sel);
    cudaGetSymbolAddress((void**)&p_conf,  g_conflict);
    cudaGetSymbolAddress((void**)&p_done,  g_done);

    // init state
    k_init<<<(NVAR*Hh + 255)/256, 256>>>(p_var, p_assign, p_done, p_conf);

    // clause encoder (once)
    k_mean<<<NTOK, 256>>>(formula, lit_emb, p_mean);
    k_gemm_tc<<<dim3(TWOH/64, NTOK/64), 128>>>(p_mean, ce_w1, ce_b1, p_x1, nullptr, NTOK, TWOH, Hh, 0, nullptr);
    k_ln_gelu<<<NTOK, 256>>>(p_x1, ce_g, ce_beta);
    k_gemm_tc<<<dim3(Hh/64, NTOK/64), 128>>>(p_x1, ce_w2, ce_b2, p_base, nullptr, NTOK, Hh, TWOH, 0, nullptr);
    k_gemm_tc<<<dim3(Hh/64, NTOK/64), 128>>>(p_base, attn_in_w + Hh*Hh,   nullptr, p_Kb, nullptr, NTOK, Hh, Hh, 0, nullptr);
    k_gemm_tc<<<dim3(Hh/64, NTOK/64), 128>>>(p_base, attn_in_w + 2*Hh*Hh, nullptr, p_Vb, nullptr, NTOK, Hh, Hh, 0, nullptr);
    k_splitK<<<NTOK*128/256, 256>>>(p_Kb, p_Kh, p_Kl);
    k_splitVT<<<64, 256>>>(p_Vb, p_VhT, p_VlT);

    for (int it = 0; it < ITERS; it++) {
        k_attn<<<Bb*HEADS*(Vv/64), 128>>>(p_var, attn_in_w, p_Kh, p_Kl, p_VhT, p_VlT,
                                          formula, p_assign, attn_in_b, p_attno, p_done);
        // attn-out projection; fused commit: var = vs (both gated on done)
        k_gemm_tc<<<dim3(Hh/64, NVAR/64), 128>>>(p_attno, attn_out_w, attn_out_b, p_vs, p_var, NVAR, Hh, Hh, 0, p_done);
        k_gemm_tc<<<dim3(Hh/64, NVAR/64), 128>>>(p_vs, vs_w1, vs_b1, p_h1, nullptr, NVAR, Hh, Hh, 1, p_done);
        k_decide<<<Bb, 256>>>(p_h1, vs_w2, vs_b2, p_vs, p_assign, ap_w1, ap_b1, ap_w2, ap_b2,
                              formula, p_sel, p_done, p_conf);
        k_finalize<<<1, 256>>>(p_assign, p_sel, p_done, p_conf);
    }

    k_satout<<<Bb, 256>>>(p_var, sp_w1, sp_b1, sp_w2, sp_b2, out);
    k_assignout<<<NVAR/256, 256>>>(p_assign, out);

    (void)in_sizes; (void)n_in; (void)out_size;
}

// round 10
// speedup vs baseline: 1.0209x; 1.0209x over previous
#include <cuda_runtime.h>
#include <cuda_bf16.h>

// Problem constants
#define Bb 8
#define Cc 2048
#define Ll 3
#define Vv 512
#define Hh 256
#define HEADS 8
#define HD 32
#define ITERS 8
#define TWOH 512
#define NTOK (Bb*Cc)      // 16384
#define NVAR (Bb*Vv)      // 4096

// ---------------- scratch (static device globals; no allocation) ----------------
__device__ float g_mean[NTOK*Hh];
__device__ float g_x1[NTOK*TWOH];
__device__ float g_base[NTOK*Hh];
__device__ float g_Kb[NTOK*Hh];
__device__ float g_Vb[NTOK*Hh];
__device__ unsigned g_Kh[NTOK*128];    // bf16-hi plane of Kb, dim-pair packed
__device__ unsigned g_Kl[NTOK*128];    // bf16-lo plane
__device__ unsigned g_VhT[64*32*1024]; // V hi, transposed: [(b,h)][dim][clause-pair]
__device__ unsigned g_VlT[64*32*1024];
__device__ unsigned g_Qh[NVAR*128];    // q planes (per-iter)
__device__ unsigned g_Ql[NVAR*128];
__device__ float    g_qb[NVAR*HEADS];  // q . bk per (row, head)
__device__ unsigned g_Wqh[Hh*128], g_Wql[Hh*128];      // pre-split weights
__device__ unsigned g_Woh[Hh*128], g_Wol[Hh*128];
__device__ unsigned g_Wv1h[Hh*128], g_Wv1l[Hh*128];
__device__ float g_var[NVAR*Hh];
__device__ float g_attno[NVAR*Hh];
__device__ float g_vs[NVAR*Hh];
__device__ float g_h1[NVAR*Hh];
__device__ int   g_assign[NVAR];
__device__ int   g_sel[Bb];
__device__ int   g_conflict;
__device__ int   g_done;

__device__ __forceinline__ float gelu_f(float x) {
    return 0.5f * x * (1.0f + erff(x * 0.70710678118654752440f));
}

// ---------------- bf16 split helpers ----------------
__device__ __forceinline__ void sp2(float x, float y, unsigned &uh, unsigned &ul) {
    float xh = __bfloat162float(__float2bfloat16_rn(x));
    float yh = __bfloat162float(__float2bfloat16_rn(y));
    float xl = x - xh, yl = y - yh;
    asm("cvt.rn.bf16x2.f32 %0, %1, %2;" : "=r"(uh) : "f"(yh), "f"(xh));
    asm("cvt.rn.bf16x2.f32 %0, %1, %2;" : "=r"(ul) : "f"(yl), "f"(xl));
}

__device__ __forceinline__ void mma_bf16(float &c0, float &c1, float &c2, float &c3,
                                         unsigned a0, unsigned a1, unsigned a2, unsigned a3,
                                         unsigned b0, unsigned b1) {
    asm volatile("mma.sync.aligned.m16n8k16.row.col.f32.bf16.bf16.f32 "
                 "{%0,%1,%2,%3}, {%4,%5,%6,%7}, {%8,%9}, {%0,%1,%2,%3};"
                 : "+f"(c0), "+f"(c1), "+f"(c2), "+f"(c3)
                 : "r"(a0), "r"(a1), "r"(a2), "r"(a3), "r"(b0), "r"(b1));
}

// ---------------- init ----------------
__global__ void k_init(float* var, int* assign, int* done, int* conflict) {
    int i = blockIdx.x * 256 + threadIdx.x;
    if (i < NVAR*Hh) var[i] = 0.f;
    if (i < NVAR) assign[i] = 2;
    if (i == 0) { *done = 0; *conflict = 0; }
}

// ---------------- split a [N x K] float matrix into bf16 planes (dim-pair packed) ----------------
__global__ void k_splitW(const float* __restrict__ W, unsigned* __restrict__ Wh,
                         unsigned* __restrict__ Wl) {
    int i = blockIdx.x * 256 + threadIdx.x;
    unsigned uh, ul;
    sp2(W[2*i], W[2*i+1], uh, ul);
    Wh[i] = uh; Wl[i] = ul;
}

// ---------------- split + transpose V: [(b,h)][dim 32][clause-pair 1024] ----------------
__global__ void k_splitVT(const float* __restrict__ Vb, unsigned* __restrict__ VhT,
                          unsigned* __restrict__ VlT) {
    int bh = blockIdx.x;          // 0..63
    int b = bh >> 3, h = bh & 7;
    int t = threadIdx.x;          // 256
    __shared__ float tile[64][33];
    for (int cc = 0; cc < Cc; cc += 64) {
        __syncthreads();
        #pragma unroll
        for (int rep = 0; rep < 8; rep++) {
            int idx = rep*256 + t;
            int cl = idx >> 5, d = idx & 31;
            tile[cl][d] = Vb[(long)(b*Cc + cc + cl)*Hh + h*32 + d];
        }
        __syncthreads();
        int d = t >> 3, j = t & 7;
        unsigned oh[4], ol[4];
        #pragma unroll
        for (int qq = 0; qq < 4; qq++) {
            int cp = j*4 + qq;
            sp2(tile[2*cp][d], tile[2*cp+1][d], oh[qq], ol[qq]);
        }
        long obase = ((long)(bh*32 + d) << 10) + (cc >> 1) + j*4;
        *(uint4*)(VhT + obase) = make_uint4(oh[0],oh[1],oh[2],oh[3]);
        *(uint4*)(VlT + obase) = make_uint4(ol[0],ol[1],ol[2],ol[3]);
    }
}

// ---------------- literal gather + mean over L ----------------
__global__ void k_mean(const int* __restrict__ formula, const float* __restrict__ lit_emb,
                       float* __restrict__ out) {
    int token = blockIdx.x;
    int d = threadIdx.x;
    int f0 = formula[token*3+0], f1 = formula[token*3+1], f2 = formula[token*3+2];
    float s = lit_emb[f0*Hh+d] + lit_emb[f1*Hh+d] + lit_emb[f2*Hh+d];
    out[(long)token*Hh + d] = s * (1.0f/3.0f);
}

// ---------------- LayerNorm (rows of 512) + gelu, in-place ----------------
__global__ void k_ln_gelu(float* __restrict__ x, const float* __restrict__ g,
                          const float* __restrict__ beta) {
    int row = blockIdx.x; int t = threadIdx.x;
    __shared__ float red[256];
    float a = x[(long)row*TWOH + t];
    float b_ = x[(long)row*TWOH + t + 256];
    red[t] = a + b_;
    __syncthreads();
    for (int s = 128; s; s >>= 1) { if (t < s) red[t] += red[t+s]; __syncthreads(); }
    float mean = red[0] * (1.0f/512.0f);
    __syncthreads();
    float da = a - mean, db = b_ - mean;
    red[t] = da*da + db*db;
    __syncthreads();
    for (int s = 128; s; s >>= 1) { if (t < s) red[t] += red[t+s]; __syncthreads(); }
    float var = red[0] * (1.0f/512.0f);
    float rstd = rsqrtf(var + 1e-5f);
    float ya = da * rstd * g[t]     + beta[t];
    float yb = db * rstd * g[t+256] + beta[t+256];
    x[(long)row*TWOH + t]       = gelu_f(ya);
    x[(long)row*TWOH + t + 256] = gelu_f(yb);
}

// ---------------- tensor-core 3-pass bf16 GEMM (float W, used by encoder) ----------------
__global__ void __launch_bounds__(128) k_gemm_tc(
        const float* __restrict__ A, const float* __restrict__ W,
        const float* __restrict__ bias, float* __restrict__ C,
        int M, int N, int K, int act) {
    __shared__ unsigned Ash[64][20], Asl[64][20];
    __shared__ unsigned Wsh[64][20], Wsl[64][20];
    int t = threadIdx.x, lane = t & 31, w = t >> 5;
    int gid = lane >> 2, tid = lane & 3;
    int m0 = blockIdx.y * 64, n0 = blockIdx.x * 64;
    float acc[8][4] = {};
    for (int k0 = 0; k0 < K; k0 += 32) {
        __syncthreads();
        #pragma unroll
        for (int rep = 0; rep < 4; rep++) {
            int idx = t + rep*128;
            int r = idx >> 3, c4 = (idx & 7) << 2;
            float4 av = *(const float4*)(A + (long)(m0+r)*K + k0 + c4);
            unsigned h0,l0,h1,l1;
            sp2(av.x, av.y, h0, l0); sp2(av.z, av.w, h1, l1);
            Ash[r][(c4>>1)] = h0; Ash[r][(c4>>1)+1] = h1;
            Asl[r][(c4>>1)] = l0; Asl[r][(c4>>1)+1] = l1;
            float4 wv = *(const float4*)(W + (long)(n0+r)*K + k0 + c4);
            sp2(wv.x, wv.y, h0, l0); sp2(wv.z, wv.w, h1, l1);
            Wsh[r][(c4>>1)] = h0; Wsh[r][(c4>>1)+1] = h1;
            Wsl[r][(c4>>1)] = l0; Wsl[r][(c4>>1)+1] = l1;
        }
        __syncthreads();
        #pragma unroll
        for (int kt = 0; kt < 2; kt++) {
            int ra = w*16 + gid, ku = kt*8 + tid;
            unsigned ah0 = Ash[ra  ][ku],  ah1 = Ash[ra+8][ku];
            unsigned ah2 = Ash[ra  ][ku+4], ah3 = Ash[ra+8][ku+4];
            unsigned al0 = Asl[ra  ][ku],  al1 = Asl[ra+8][ku];
            unsigned al2 = Asl[ra  ][ku+4], al3 = Asl[ra+8][ku+4];
            #pragma unroll
            for (int nt = 0; nt < 8; nt++) {
                int rb = nt*8 + gid;
                unsigned bh0 = Wsh[rb][ku], bh1 = Wsh[rb][ku+4];
                unsigned bl0 = Wsl[rb][ku], bl1 = Wsl[rb][ku+4];
                mma_bf16(acc[nt][0],acc[nt][1],acc[nt][2],acc[nt][3], ah0,ah1,ah2,ah3, bh0,bh1);
                mma_bf16(acc[nt][0],acc[nt][1],acc[nt][2],acc[nt][3], ah0,ah1,ah2,ah3, bl0,bl1);
                mma_bf16(acc[nt][0],acc[nt][1],acc[nt][2],acc[nt][3], al0,al1,al2,al3, bh0,bh1);
            }
        }
    }
    int r = m0 + w*16 + gid;
    #pragma unroll
    for (int nt = 0; nt < 8; nt++) {
        int c = n0 + nt*8 + 2*tid;
        float b0v = bias ? bias[c] : 0.0f;
        float b1v = bias ? bias[c+1] : 0.0f;
        float v0 = acc[nt][0] + b0v, v1 = acc[nt][1] + b1v;
        float v2 = acc[nt][2] + b0v, v3 = acc[nt][3] + b1v;
        if (act) { v0 = gelu_f(v0); v1 = gelu_f(v1); v2 = gelu_f(v2); v3 = gelu_f(v3); }
        *(float2*)(C + (long)r*N + c)     = make_float2(v0, v1);
        *(float2*)(C + (long)(r+8)*N + c) = make_float2(v2, v3);
    }
}

// ---------------- per-iter GEMM with PRE-SPLIT weights (float out, optional dup) ----------------
// N = K = 256 fixed for per-iter use; generic M.
__global__ void __launch_bounds__(128) k_gemm_ps(
        const float* __restrict__ A,
        const unsigned* __restrict__ Wh, const unsigned* __restrict__ Wl,
        const float* __restrict__ bias, float* __restrict__ C,
        float* __restrict__ C2, int M, int N, int K, int act,
        const int* __restrict__ done) {
    if (*done) return;
    __shared__ unsigned Ash[64][20], Asl[64][20];
    __shared__ unsigned Wsh[64][20], Wsl[64][20];
    int t = threadIdx.x, lane = t & 31, w = t >> 5;
    int gid = lane >> 2, tid = lane & 3;
    int m0 = blockIdx.y * 64, n0 = blockIdx.x * 64;
    int Kh2 = K >> 1;
    float acc[8][4] = {};
    for (int k0 = 0; k0 < K; k0 += 32) {
        __syncthreads();
        #pragma unroll
        for (int rep = 0; rep < 4; rep++) {
            int idx = t + rep*128;
            int r = idx >> 3, c4 = (idx & 7) << 2;
            float4 av = *(const float4*)(A + (long)(m0+r)*K + k0 + c4);
            unsigned h0,l0,h1,l1;
            sp2(av.x, av.y, h0, l0); sp2(av.z, av.w, h1, l1);
            Ash[r][(c4>>1)] = h0; Ash[r][(c4>>1)+1] = h1;
            Asl[r][(c4>>1)] = l0; Asl[r][(c4>>1)+1] = l1;
        }
        #pragma unroll
        for (int rep = 0; rep < 2; rep++) {
            int idx4 = t + rep*128;              // 0..255
            int r = idx4 >> 2, u4 = (idx4 & 3) << 2;
            long gix = (long)(n0+r)*Kh2 + (k0>>1) + u4;
            *(uint4*)(&Wsh[r][u4]) = *(const uint4*)(Wh + gix);
            *(uint4*)(&Wsl[r][u4]) = *(const uint4*)(Wl + gix);
        }
        __syncthreads();
        #pragma unroll
        for (int kt = 0; kt < 2; kt++) {
            int ra = w*16 + gid, ku = kt*8 + tid;
            unsigned ah0 = Ash[ra  ][ku],  ah1 = Ash[ra+8][ku];
            unsigned ah2 = Ash[ra  ][ku+4], ah3 = Ash[ra+8][ku+4];
            unsigned al0 = Asl[ra  ][ku],  al1 = Asl[ra+8][ku];
            unsigned al2 = Asl[ra  ][ku+4], al3 = Asl[ra+8][ku+4];
            #pragma unroll
            for (int nt = 0; nt < 8; nt++) {
                int rb = nt*8 + gid;
                unsigned bh0 = Wsh[rb][ku], bh1 = Wsh[rb][ku+4];
                unsigned bl0 = Wsl[rb][ku], bl1 = Wsl[rb][ku+4];
                mma_bf16(acc[nt][0],acc[nt][1],acc[nt][2],acc[nt][3], ah0,ah1,ah2,ah3, bh0,bh1);
                mma_bf16(acc[nt][0],acc[nt][1],acc[nt][2],acc[nt][3], ah0,ah1,ah2,ah3, bl0,bl1);
                mma_bf16(acc[nt][0],acc[nt][1],acc[nt][2],acc[nt][3], al0,al1,al2,al3, bh0,bh1);
            }
        }
    }
    int r = m0 + w*16 + gid;
    #pragma unroll
    for (int nt = 0; nt < 8; nt++) {
        int c = n0 + nt*8 + 2*tid;
        float b0v = bias[c], b1v = bias[c+1];
        float v0 = acc[nt][0] + b0v, v1 = acc[nt][1] + b1v;
        float v2 = acc[nt][2] + b0v, v3 = acc[nt][3] + b1v;
        if (act) { v0 = gelu_f(v0); v1 = gelu_f(v1); v2 = gelu_f(v2); v3 = gelu_f(v3); }
        *(float2*)(C + (long)r*N + c)     = make_float2(v0, v1);
        *(float2*)(C + (long)(r+8)*N + c) = make_float2(v2, v3);
        if (C2) {
            *(float2*)(C2 + (long)r*N + c)     = make_float2(v0, v1);
            *(float2*)(C2 + (long)(r+8)*N + c) = make_float2(v2, v3);
        }
    }
}

// ---------------- Q GEMM: var @ Wq^T + bq -> split planes + per-head qb ----------------
// grid dim3(4, NVAR/64), 128 threads. N=K=256.
__global__ void __launch_bounds__(128) k_gemm_q(
        const float* __restrict__ A,
        const unsigned* __restrict__ Wh, const unsigned* __restrict__ Wl,
        const float* __restrict__ attn_in_b,
        unsigned* __restrict__ Qh, unsigned* __restrict__ Ql,
        float* __restrict__ qb, const int* __restrict__ done) {
    if (*done) return;
    __shared__ unsigned Ash[64][20], Asl[64][20];
    __shared__ unsigned Wsh[64][20], Wsl[64][20];
    int t = threadIdx.x, lane = t & 31, w = t >> 5;
    int gid = lane >> 2, tid = lane & 3;
    int m0 = blockIdx.y * 64, n0 = blockIdx.x * 64;
    float acc[8][4] = {};
    for (int k0 = 0; k0 < Hh; k0 += 32) {
        __syncthreads();
        #pragma unroll
        for (int rep = 0; rep < 4; rep++) {
            int idx = t + rep*128;
            int r = idx >> 3, c4 = (idx & 7) << 2;
            float4 av = *(const float4*)(A + (long)(m0+r)*Hh + k0 + c4);
            unsigned h0,l0,h1,l1;
            sp2(av.x, av.y, h0, l0); sp2(av.z, av.w, h1, l1);
            Ash[r][(c4>>1)] = h0; Ash[r][(c4>>1)+1] = h1;
            Asl[r][(c4>>1)] = l0; Asl[r][(c4>>1)+1] = l1;
        }
        #pragma unroll
        for (int rep = 0; rep < 2; rep++) {
            int idx4 = t + rep*128;
            int r = idx4 >> 2, u4 = (idx4 & 3) << 2;
            long gix = (long)(n0+r)*128 + (k0>>1) + u4;
            *(uint4*)(&Wsh[r][u4]) = *(const uint4*)(Wh + gix);
            *(uint4*)(&Wsl[r][u4]) = *(const uint4*)(Wl + gix);
        }
        __syncthreads();
        #pragma unroll
        for (int kt = 0; kt < 2; kt++) {
            int ra = w*16 + gid, ku = kt*8 + tid;
            unsigned ah0 = Ash[ra  ][ku],  ah1 = Ash[ra+8][ku];
            unsigned ah2 = Ash[ra  ][ku+4], ah3 = Ash[ra+8][ku+4];
            unsigned al0 = Asl[ra  ][ku],  al1 = Asl[ra+8][ku];
            unsigned al2 = Asl[ra  ][ku+4], al3 = Asl[ra+8][ku+4];
            #pragma unroll
            for (int nt = 0; nt < 8; nt++) {
                int rb = nt*8 + gid;
                unsigned bh0 = Wsh[rb][ku], bh1 = Wsh[rb][ku+4];
                unsigned bl0 = Wsl[rb][ku], bl1 = Wsl[rb][ku+4];
                mma_bf16(acc[nt][0],acc[nt][1],acc[nt][2],acc[nt][3], ah0,ah1,ah2,ah3, bh0,bh1);
                mma_bf16(acc[nt][0],acc[nt][1],acc[nt][2],acc[nt][3], ah0,ah1,ah2,ah3, bl0,bl1);
                mma_bf16(acc[nt][0],acc[nt][1],acc[nt][2],acc[nt][3], al0,al1,al2,al3, bh0,bh1);
            }
        }
    }
    int r = m0 + w*16 + gid;
    const float* bq = attn_in_b + n0;
    const float* bk = attn_in_b + Hh + n0;
    float hs[4] = {0.f, 0.f, 0.f, 0.f};   // [r/headA, r/headB, r+8/headA, r+8/headB]
    #pragma unroll
    for (int nt = 0; nt < 8; nt++) {
        int c = nt*8 + 2*tid;
        float b0 = bq[c], b1 = bq[c+1];
        float v0 = acc[nt][0] + b0, v1 = acc[nt][1] + b1;
        float v2 = acc[nt][2] + b0, v3 = acc[nt][3] + b1;
        float k0v = bk[c], k1v = bk[c+1];
        int hi = nt >> 2;
        hs[hi]   += v0*k0v + v1*k1v;
        hs[hi+2] += v2*k0v + v3*k1v;
        int cp = (n0 >> 1) + nt*4 + tid;
        unsigned uh, ul;
        sp2(v0, v1, uh, ul);
        Qh[(long)r*128 + cp] = uh; Ql[(long)r*128 + cp] = ul;
        sp2(v2, v3, uh, ul);
        Qh[(long)(r+8)*128 + cp] = uh; Ql[(long)(r+8)*128 + cp] = ul;
    }
    #pragma unroll
    for (int i = 0; i < 4; i++) {
        hs[i] += __shfl_xor_sync(0xffffffffu, hs[i], 1);
        hs[i] += __shfl_xor_sync(0xffffffffu, hs[i], 2);
    }
    if (tid == 0) {
        int hA = n0 >> 5;
        qb[r*8 + hA]     = hs[0];  qb[r*8 + hA + 1]     = hs[1];
        qb[(r+8)*8 + hA] = hs[2];  qb[(r+8)*8 + hA + 1] = hs[3];
    }
}

// ---------------- flash attention: 3-pass bf16, pre-split Q/K/V, fused clause-scale ----------------
// grid: B*HEADS*(V/64) = 512 blocks, 128 threads (4 warps x 16 q-rows).
#define BC 64
__global__ void __launch_bounds__(128) k_attn(
        const unsigned* __restrict__ Qhp, const unsigned* __restrict__ Qlp,
        const float* __restrict__ qbp,
        const unsigned* __restrict__ Kh, const unsigned* __restrict__ Kl,
        const unsigned* __restrict__ VhT, const unsigned* __restrict__ VlT,
        const int* __restrict__ formula, const int* __restrict__ assign,
        const float* __restrict__ attn_in_b, float* __restrict__ out,
        const int* __restrict__ done) {
    if (*done) return;
    int bid = blockIdx.x;
    int qt = bid & 7;
    int h  = (bid >> 3) & 7;
    int b  = bid >> 6;
    int t = threadIdx.x, lane = t & 31, w = t >> 5;
    int gid = lane >> 2, tid = lane & 3;

    __shared__ unsigned Ksh[BC][20], Ksl[BC][20];
    __shared__ unsigned Vsh[HD][36], Vsl[HD][36];
    __shared__ float    scs[BC];

    int row0 = qt * 64;
    int rA = b*Vv + row0 + w*16 + gid;
    // Q fragments straight from pre-split planes
    unsigned qh[2][4], ql[2][4];
    {
        long q0 = ((long)rA << 7) + h*16;
        long q1 = q0 + (8 << 7);
        #pragma unroll
        for (int kt = 0; kt < 2; kt++) {
            int u = kt*8 + tid;
            qh[kt][0] = Qhp[q0 + u];     qh[kt][1] = Qhp[q1 + u];
            qh[kt][2] = Qhp[q0 + u + 4]; qh[kt][3] = Qhp[q1 + u + 4];
            ql[kt][0] = Qlp[q0 + u];     ql[kt][1] = Qlp[q1 + u];
            ql[kt][2] = Qlp[q0 + u + 4]; ql[kt][3] = Qlp[q1 + u + 4];
        }
    }
    float qb0 = qbp[rA*8 + h];
    float qb1 = qbp[(rA+8)*8 + h];

    float m0 = -1e30f, m1 = -1e30f, s0a = 0.f, s1a = 0.f;
    float o_[4][4] = {};
    const float inv = 0.17677669529663688110f;   // 1/sqrt(32)
    long vbase = ((long)((b*8 + h)*HD) << 10);

    for (int c0 = 0; c0 < Cc; c0 += BC) {
        __syncthreads();
        if (t < BC) {
            int cg = b*Cc + c0 + t;
            int f0 = formula[cg*3+0], f1 = formula[cg*3+1], f2 = formula[cg*3+2];
            int a0 = assign[b*Vv + (f0>>1)];
            int a1 = assign[b*Vv + (f1>>1)];
            int a2 = assign[b*Vv + (f2>>1)];
            bool sat = (a0 == (f0&1)) || (a1 == (f1&1)) || (a2 == (f2&1));
            scs[t] = sat ? 0.1f : 1.0f;
        }
        #pragma unroll
        for (int rep = 0; rep < 2; rep++) {
            int idx4 = t + rep*128;
            int c = idx4 >> 2, u4 = (idx4 & 3) << 2;
            long gix = ((long)(b*Cc + c0 + c) << 7) + (h << 4) + u4;
            *(uint4*)(&Ksh[c][u4]) = *(const uint4*)(Kh + gix);
            *(uint4*)(&Ksl[c][u4]) = *(const uint4*)(Kl + gix);
        }
        #pragma unroll
        for (int rep = 0; rep < 2; rep++) {
            int idx4 = t + rep*128;
            int d = idx4 >> 3, j4 = (idx4 & 7) << 2;
            long gix = vbase + ((long)d << 10) + (c0 >> 1) + j4;
            *(uint4*)(&Vsh[d][j4]) = *(const uint4*)(VhT + gix);
            *(uint4*)(&Vsl[d][j4]) = *(const uint4*)(VlT + gix);
        }
        __syncthreads();

        float sc_[8][4];
        #pragma unroll
        for (int nt = 0; nt < 8; nt++) {
            float a0 = 0.f, a1 = 0.f, a2 = 0.f, a3 = 0.f;
            #pragma unroll
            for (int kt = 0; kt < 2; kt++) {
                int cn = nt*8 + gid, ku = kt*8 + tid;
                unsigned bh0 = Ksh[cn][ku], bh1 = Ksh[cn][ku+4];
                unsigned bl0 = Ksl[cn][ku], bl1 = Ksl[cn][ku+4];
                mma_bf16(a0,a1,a2,a3, qh[kt][0],qh[kt][1],qh[kt][2],qh[kt][3], bh0,bh1);
                mma_bf16(a0,a1,a2,a3, qh[kt][0],qh[kt][1],qh[kt][2],qh[kt][3], bl0,bl1);
                mma_bf16(a0,a1,a2,a3, ql[kt][0],ql[kt][1],ql[kt][2],ql[kt][3], bh0,bh1);
            }
            sc_[nt][0]=a0; sc_[nt][1]=a1; sc_[nt][2]=a2; sc_[nt][3]=a3;
        }

        float rm0 = -1e30f, rm1 = -1e30f;
        #pragma unroll
        for (int nt = 0; nt < 8; nt++) {
            float scA = scs[nt*8 + 2*tid];
            float scB = scs[nt*8 + 2*tid + 1];
            sc_[nt][0] = fmaf(sc_[nt][0], scA, qb0) * inv;
            sc_[nt][1] = fmaf(sc_[nt][1], scB, qb0) * inv;
            sc_[nt][2] = fmaf(sc_[nt][2], scA, qb1) * inv;
            sc_[nt][3] = fmaf(sc_[nt][3], scB, qb1) * inv;
            rm0 = fmaxf(rm0, fmaxf(sc_[nt][0], sc_[nt][1]));
            rm1 = fmaxf(rm1, fmaxf(sc_[nt][2], sc_[nt][3]));
        }
        rm0 = fmaxf(rm0, __shfl_xor_sync(0xffffffffu, rm0, 1));
        rm0 = fmaxf(rm0, __shfl_xor_sync(0xffffffffu, rm0, 2));
        rm1 = fmaxf(rm1, __shfl_xor_sync(0xffffffffu, rm1, 1));
        rm1 = fmaxf(rm1, __shfl_xor_sync(0xffffffffu, rm1, 2));
        float mn0 = fmaxf(m0, rm0), mn1 = fmaxf(m1, rm1);
        float corr0 = __expf(m0 - mn0), corr1 = __expf(m1 - mn1);
        float ps0 = 0.f, ps1 = 0.f;
        #pragma unroll
        for (int nt = 0; nt < 8; nt++) {
            sc_[nt][0] = __expf(sc_[nt][0] - mn0);
            sc_[nt][1] = __expf(sc_[nt][1] - mn0);
            sc_[nt][2] = __expf(sc_[nt][2] - mn1);
            sc_[nt][3] = __expf(sc_[nt][3] - mn1);
            ps0 += sc_[nt][0] + sc_[nt][1];
            ps1 += sc_[nt][2] + sc_[nt][3];
        }
        ps0 += __shfl_xor_sync(0xffffffffu, ps0, 1);
        ps0 += __shfl_xor_sync(0xffffffffu, ps0, 2);
        ps1 += __shfl_xor_sync(0xffffffffu, ps1, 1);
        ps1 += __shfl_xor_sync(0xffffffffu, ps1, 2);
        s0a = s0a*corr0 + ps0;
        s1a = s1a*corr1 + ps1;
        m0 = mn0; m1 = mn1;

        #pragma unroll
        for (int nt2 = 0; nt2 < 4; nt2++) {
            o_[nt2][0] *= corr0; o_[nt2][1] *= corr0;
            o_[nt2][2] *= corr1; o_[nt2][3] *= corr1;
        }

        #pragma unroll
        for (int kt = 0; kt < 4; kt++) {
            int cA = kt*16 + 2*tid;
            float sA = scs[cA], sB = scs[cA+1], sC = scs[cA+8], sD = scs[cA+9];
            unsigned ah0, al0, ah1, al1, ah2, al2, ah3, al3;
            sp2(sc_[2*kt  ][0]*sA, sc_[2*kt  ][1]*sB, ah0, al0);
            sp2(sc_[2*kt  ][2]*sA, sc_[2*kt  ][3]*sB, ah1, al1);
            sp2(sc_[2*kt+1][0]*sC, sc_[2*kt+1][1]*sD, ah2, al2);
            sp2(sc_[2*kt+1][2]*sC, sc_[2*kt+1][3]*sD, ah3, al3);
            #pragma unroll
            for (int nt2 = 0; nt2 < 4; nt2++) {
                int d = nt2*8 + gid, ku = kt*8 + tid;
                unsigned bh0 = Vsh[d][ku], bh1 = Vsh[d][ku+4];
                unsigned bl0 = Vsl[d][ku], bl1 = Vsl[d][ku+4];
                mma_bf16(o_[nt2][0],o_[nt2][1],o_[nt2][2],o_[nt2][3], ah0,ah1,ah2,ah3, bh0,bh1);
                mma_bf16(o_[nt2][0],o_[nt2][1],o_[nt2][2],o_[nt2][3], ah0,ah1,ah2,ah3, bl0,bl1);
                mma_bf16(o_[nt2][0],o_[nt2][1],o_[nt2][2],o_[nt2][3], al0,al1,al2,al3, bh0,bh1);
            }
        }
    }

    const float* bvp = attn_in_b + 2*Hh + h*HD;
    float is0 = 1.0f / s0a, is1 = 1.0f / s1a;
    #pragma unroll
    for (int nt2 = 0; nt2 < 4; nt2++) {
        int d = nt2*8 + 2*tid;
        float2 bvv = *(const float2*)(bvp + d);
        float2 w0 = make_float2(o_[nt2][0]*is0 + bvv.x, o_[nt2][1]*is0 + bvv.y);
        float2 w1v = make_float2(o_[nt2][2]*is1 + bvv.x, o_[nt2][3]*is1 + bvv.y);
        *(float2*)(out + ((long)rA << 8) + (h << 5) + d) = w0;
        *(float2*)(out + ((long)(rA + 8) << 8) + (h << 5) + d) = w1v;
    }
}

// ---------------- fused decide: scores + argmax + ap head + assign + conflict ----------------
__global__ void k_decide(const float* __restrict__ h1, const float* __restrict__ vw2,
                         const float* __restrict__ vb2,
                         const float* __restrict__ vs, int* __restrict__ assign,
                         const float* __restrict__ w1, const float* __restrict__ b1,
                         const float* __restrict__ w2, const float* __restrict__ b2,
                         const int* __restrict__ formula,
                         int* __restrict__ sel_out, const int* __restrict__ done,
                         int* __restrict__ conflict) {
    int b = blockIdx.x, t = threadIdx.x;
    if (*done) return;
    __shared__ float sc[512];
    __shared__ float sv[256];
    __shared__ int   si[256];
    __shared__ float vsel[256];
    __shared__ float hbuf[256];
    __shared__ float r0s[256];
    __shared__ float r1s[256];
    int w = t >> 5, lane = t & 31;
    for (int r = w; r < Vv; r += 8) {
        const float* hr = h1 + ((long)(b*Vv + r)) * Hh;
        float acc = 0.f;
        #pragma unroll
        for (int i = 0; i < 8; i++) acc = fmaf(hr[lane + 32*i], vw2[lane + 32*i], acc);
        #pragma unroll
        for (int o = 16; o; o >>= 1) acc += __shfl_xor_sync(0xffffffffu, acc, o);
        if (lane == 0) {
            float s = acc + vb2[0];
            if (assign[b*Vv + r] != 2) s += -1000000000.0f;
            sc[r] = s;
        }
    }
    __syncthreads();
    float v1 = sc[t], v2 = sc[t + 256];
    float bvv; int bi;
    if (v2 > v1) { bvv = v2; bi = t + 256; } else { bvv = v1; bi = t; }
    sv[t] = bvv; si[t] = bi;
    __syncthreads();
    for (int s = 128; s; s >>= 1) {
        if (t < s) {
            if (sv[t+s] > sv[t] || (sv[t+s] == sv[t] && si[t+s] < si[t])) {
                sv[t] = sv[t+s]; si[t] = si[t+s];
            }
        }
        __syncthreads();
    }
    int sel = si[0];
    vsel[t] = vs[((long)(b*Vv + sel)) * Hh + t];
    __syncthreads();
    for (int oo = 0; oo < 32; oo++) {
        int o = w*32 + oo;
        float acc = 0.f;
        #pragma unroll
        for (int kk = 0; kk < 8; kk++)
            acc = fmaf(w1[o*Hh + lane + 32*kk], vsel[lane + 32*kk], acc);
        #pragma unroll
        for (int off = 16; off; off >>= 1) acc += __shfl_xor_sync(0xffffffffu, acc, off);
        if (lane == 0) hbuf[o] = gelu_f(acc + b1[o]);
    }
    __syncthreads();
    float hv = hbuf[t];
    r0s[t] = hv * w2[t];
    r1s[t] = hv * w2[Hh + t];
    __syncthreads();
    for (int s = 128; s; s >>= 1) {
        if (t < s) { r0s[t] += r0s[t+s]; r1s[t] += r1s[t+s]; }
        __syncthreads();
    }
    if (t == 0) {
        float l0 = r0s[0] + b2[0], l1 = r1s[0] + b2[1];
        assign[b*Vv + sel] = (l1 > l0) ? 1 : 0;
        sel_out[b] = sel;
    }
    __syncthreads();
    int myconf = 0;
    for (int i = t; i < Cc; i += 256) {
        int cg = b*Cc + i;
        int f0 = formula[cg*3+0], f1 = formula[cg*3+1], f2 = formula[cg*3+2];
        int a0 = assign[b*Vv + (f0>>1)];
        int a1 = assign[b*Vv + (f1>>1)];
        int a2 = assign[b*Vv + (f2>>1)];
        bool sat = (a0 == (f0&1)) || (a1 == (f1&1)) || (a2 == (f2&1));
        bool allass = (a0 != 2) && (a1 != 2) && (a2 != 2);
        if (allass && !sat) myconf = 1;
    }
    if (__syncthreads_or(myconf)) {
        if (t == 0) atomicOr(conflict, 1);
    }
}

// ---------------- rollback + done update (resets conflict for next iter) ----------------
__global__ void k_finalize(int* __restrict__ assign, const int* __restrict__ sel,
                           int* __restrict__ done, int* __restrict__ conflict) {
    __shared__ int red[256];
    __shared__ int sconf;
    int t = threadIdx.x;
    if (*done) return;
    if (t == 0) { sconf = *conflict; *conflict = 0; }
    __syncthreads();
    int conf = sconf;
    if (conf && t < Bb) assign[t*Vv + sel[t]] = 2;
    __syncthreads();
    int ok = 1;
    for (int i = t; i < NVAR; i += 256) ok &= (assign[i] != 2) ? 1 : 0;
    red[t] = ok;
    __syncthreads();
    for (int s = 128; s; s >>= 1) { if (t < s) red[t] &= red[t+s]; __syncthreads(); }
    if (t == 0 && red[0] && !conf) *done = 1;
}

// ---------------- final sat-probability head ----------------
__global__ void k_satout(const float* __restrict__ var,
                         const float* __restrict__ w1, const float* __restrict__ b1,
                         const float* __restrict__ w2, const float* __restrict__ b2,
                         float* __restrict__ out) {
    int b = blockIdx.x, t = threadIdx.x;
    __shared__ float msh[256];
    __shared__ float hbuf[256];
    __shared__ float red[256];
    float ssum_ = 0.f;
    for (int v = 0; v < Vv; v++) ssum_ += var[((long)(b*Vv + v)) * Hh + t];
    msh[t] = ssum_ * (1.0f/512.0f);
    __syncthreads();
    int w = t >> 5, lane = t & 31;
    for (int oo = 0; oo < 32; oo++) {
        int o = w*32 + oo;
        float acc = 0.f;
        #pragma unroll
        for (int kk = 0; kk < 8; kk++)
            acc = fmaf(w1[o*Hh + lane + 32*kk], msh[lane + 32*kk], acc);
        #pragma unroll
        for (int off = 16; off; off >>= 1) acc += __shfl_xor_sync(0xffffffffu, acc, off);
        if (lane == 0) hbuf[o] = gelu_f(acc + b1[o]);
    }
    __syncthreads();
    red[t] = hbuf[t] * w2[t];
    __syncthreads();
    for (int s = 128; s; s >>= 1) { if (t < s) red[t] += red[t+s]; __syncthreads(); }
    if (t == 0) {
        float l = red[0] + b2[0];
        out[b] = 1.0f / (1.0f + expf(-l));
    }
}

__global__ void k_assignout(const int* __restrict__ assign, float* __restrict__ out) {
    int i = blockIdx.x * 256 + threadIdx.x;
    if (i < NVAR) out[Bb + i] = (float)assign[i];
}

// ---------------- host launch ----------------
extern "C" void kernel_launch(void* const* d_in, const int* in_sizes, int n_in,
                              void* d_out, int out_size) {
    const int*   formula    = (const int*)  d_in[0];
    const float* lit_emb    = (const float*)d_in[1];
    const float* ce_w1      = (const float*)d_in[2];
    const float* ce_b1      = (const float*)d_in[3];
    const float* ce_g       = (const float*)d_in[4];
    const float* ce_beta    = (const float*)d_in[5];
    const float* ce_w2      = (const float*)d_in[6];
    const float* ce_b2      = (const float*)d_in[7];
    const float* attn_in_w  = (const float*)d_in[8];
    const float* attn_in_b  = (const float*)d_in[9];
    const float* attn_out_w = (const float*)d_in[10];
    const float* attn_out_b = (const float*)d_in[11];
    const float* vs_w1      = (const float*)d_in[12];
    const float* vs_b1      = (const float*)d_in[13];
    const float* vs_w2      = (const float*)d_in[14];
    const float* vs_b2      = (const float*)d_in[15];
    const float* ap_w1      = (const float*)d_in[16];
    const float* ap_b1      = (const float*)d_in[17];
    const float* ap_w2      = (const float*)d_in[18];
    const float* ap_b2      = (const float*)d_in[19];
    const float* sp_w1      = (const float*)d_in[20];
    const float* sp_b1      = (const float*)d_in[21];
    const float* sp_w2      = (const float*)d_in[22];
    const float* sp_b2      = (const float*)d_in[23];
    float* out = (float*)d_out;

    float *p_mean, *p_x1, *p_base, *p_Kb, *p_Vb, *p_var, *p_attno, *p_vs, *p_h1, *p_qb;
    unsigned *p_Kh, *p_Kl, *p_VhT, *p_VlT, *p_Qh, *p_Ql;
    unsigned *p_Wqh, *p_Wql, *p_Woh, *p_Wol, *p_Wv1h, *p_Wv1l;
    int *p_assign, *p_sel, *p_conf, *p_done;
    cudaGetSymbolAddress((void**)&p_mean,  g_mean);
    cudaGetSymbolAddress((void**)&p_x1,    g_x1);
    cudaGetSymbolAddress((void**)&p_base,  g_base);
    cudaGetSymbolAddress((void**)&p_Kb,    g_Kb);
    cudaGetSymbolAddress((void**)&p_Vb,    g_Vb);
    cudaGetSymbolAddress((void**)&p_Kh,    g_Kh);
    cudaGetSymbolAddress((void**)&p_Kl,    g_Kl);
    cudaGetSymbolAddress((void**)&p_VhT,   g_VhT);
    cudaGetSymbolAddress((void**)&p_VlT,   g_VlT);
    cudaGetSymbolAddress((void**)&p_Qh,    g_Qh);
    cudaGetSymbolAddress((void**)&p_Ql,    g_Ql);
    cudaGetSymbolAddress((void**)&p_qb,    g_qb);
    cudaGetSymbolAddress((void**)&p_Wqh,   g_Wqh);
    cudaGetSymbolAddress((void**)&p_Wql,   g_Wql);
    cudaGetSymbolAddress((void**)&p_Woh,   g_Woh);
    cudaGetSymbolAddress((void**)&p_Wol,   g_Wol);
    cudaGetSymbolAddress((void**)&p_Wv1h,  g_Wv1h);
    cudaGetSymbolAddress((void**)&p_Wv1l,  g_Wv1l);
    cudaGetSymbolAddress((void**)&p_var,   g_var);
    cudaGetSymbolAddress((void**)&p_attno, g_attno);
    cudaGetSymbolAddress((void**)&p_vs,    g_vs);
    cudaGetSymbolAddress((void**)&p_h1,    g_h1);
    cudaGetSymbolAddress((void**)&p_assign,g_assign);
    cudaGetSymbolAddress((void**)&p_sel,   g_sel);
    cudaGetSymbolAddress((void**)&p_conf,  g_conflict);
    cudaGetSymbolAddress((void**)&p_done,  g_done);

    // init state
    k_init<<<(NVAR*Hh + 255)/256, 256>>>(p_var, p_assign, p_done, p_conf);

    // pre-split loop-invariant weights
    k_splitW<<<Hh*128/256, 256>>>(attn_in_w,  p_Wqh,  p_Wql);   // Wq = rows 0..255
    k_splitW<<<Hh*128/256, 256>>>(attn_out_w, p_Woh,  p_Wol);
    k_splitW<<<Hh*128/256, 256>>>(vs_w1,      p_Wv1h, p_Wv1l);

    // clause encoder (once)
    k_mean<<<NTOK, 256>>>(formula, lit_emb, p_mean);
    k_gemm_tc<<<dim3(TWOH/64, NTOK/64), 128>>>(p_mean, ce_w1, ce_b1, p_x1, NTOK, TWOH, Hh, 0);
    k_ln_gelu<<<NTOK, 256>>>(p_x1, ce_g, ce_beta);
    k_gemm_tc<<<dim3(Hh/64, NTOK/64), 128>>>(p_x1, ce_w2, ce_b2, p_base, NTOK, Hh, TWOH, 0);
    k_gemm_tc<<<dim3(Hh/64, NTOK/64), 128>>>(p_base, attn_in_w + Hh*Hh,   nullptr, p_Kb, NTOK, Hh, Hh, 0);
    k_gemm_tc<<<dim3(Hh/64, NTOK/64), 128>>>(p_base, attn_in_w + 2*Hh*Hh, nullptr, p_Vb, NTOK, Hh, Hh, 0);
    k_splitW<<<NTOK*128/256, 256>>>(p_Kb, p_Kh, p_Kl);
    k_splitVT<<<64, 256>>>(p_Vb, p_VhT, p_VlT);

    for (int it = 0; it < ITERS; it++) {
        k_gemm_q<<<dim3(4, NVAR/64), 128>>>(p_var, p_Wqh, p_Wql, attn_in_b,
                                            p_Qh, p_Ql, p_qb, p_done);
        k_attn<<<Bb*HEADS*(Vv/64), 128>>>(p_Qh, p_Ql, p_qb, p_Kh, p_Kl, p_VhT, p_VlT,
                                          formula, p_assign, attn_in_b, p_attno, p_done);
        // attn-out projection; fused commit: var = vs (both gated on done)
        k_gemm_ps<<<dim3(Hh/64, NVAR/64), 128>>>(p_attno, p_Woh, p_Wol, attn_out_b,
                                                 p_vs, p_var, NVAR, Hh, Hh, 0, p_done);
        k_gemm_ps<<<dim3(Hh/64, NVAR/64), 128>>>(p_vs, p_Wv1h, p_Wv1l, vs_b1,
                                                 p_h1, nullptr, NVAR, Hh, Hh, 1, p_done);
        k_decide<<<Bb, 256>>>(p_h1, vs_w2, vs_b2, p_vs, p_assign, ap_w1, ap_b1, ap_w2, ap_b2,
                              formula, p_sel, p_done, p_conf);
        k_finalize<<<1, 256>>>(p_assign, p_sel, p_done, p_conf);
    }

    k_satout<<<Bb, 256>>>(p_var, sp_w1, sp_b1, sp_w2, sp_b2, out);
    k_assignout<<<NVAR/256, 256>>>(p_assign, out);

    (void)in_sizes; (void)n_in; (void)out_size;
}

// round 11
// speedup vs baseline: 1.2488x; 1.2232x over previous
#include <cuda_runtime.h>
#include <cuda_bf16.h>

// Problem constants
#define Bb 8
#define Cc 2048
#define Ll 3
#define Vv 512
#define Hh 256
#define HEADS 8
#define HD 32
#define ITERS 8
#define TWOH 512
#define NTOK (Bb*Cc)      // 16384
#define NVAR (Bb*Vv)      // 4096

// ---------------- scratch (static device globals; no allocation) ----------------
__device__ float g_mean[NTOK*Hh];
__device__ float g_x1[NTOK*TWOH];
__device__ float g_base[NTOK*Hh];
__device__ float g_Kb[NTOK*Hh];
__device__ float g_Vb[NTOK*Hh];
__device__ unsigned g_Kh[NTOK*128];    // bf16-hi plane of Kb, dim-pair packed
__device__ unsigned g_Kl[NTOK*128];    // bf16-lo plane
__device__ unsigned g_VhT[64*32*1024]; // V hi, transposed: [(b,h)][dim][clause-pair]
__device__ unsigned g_VlT[64*32*1024];
__device__ unsigned g_Qh[NVAR*128];    // q planes (per-iter)
__device__ unsigned g_Ql[NVAR*128];
__device__ float    g_qb[NVAR*HEADS];  // q . bk per (row, head)
__device__ unsigned g_Wqh[Hh*128], g_Wql[Hh*128];      // pre-split weights
__device__ unsigned g_Woh[Hh*128], g_Wol[Hh*128];
__device__ unsigned g_Wv1h[Hh*128], g_Wv1l[Hh*128];
__device__ float g_var[NVAR*Hh];
__device__ float g_attno[NVAR*Hh];
__device__ float g_vs[NVAR*Hh];
__device__ float g_h1[NVAR*Hh];
__device__ float g_scores[NVAR];
__device__ int   g_assign[NVAR];
__device__ int   g_sel[Bb];
__device__ int   g_conflict;
__device__ int   g_done;

__device__ __forceinline__ float gelu_f(float x) {
    return 0.5f * x * (1.0f + erff(x * 0.70710678118654752440f));
}

// ---------------- bf16 split helpers ----------------
__device__ __forceinline__ void sp2(float x, float y, unsigned &uh, unsigned &ul) {
    float xh = __bfloat162float(__float2bfloat16_rn(x));
    float yh = __bfloat162float(__float2bfloat16_rn(y));
    float xl = x - xh, yl = y - yh;
    asm("cvt.rn.bf16x2.f32 %0, %1, %2;" : "=r"(uh) : "f"(yh), "f"(xh));
    asm("cvt.rn.bf16x2.f32 %0, %1, %2;" : "=r"(ul) : "f"(yl), "f"(xl));
}

__device__ __forceinline__ void mma_bf16(float &c0, float &c1, float &c2, float &c3,
                                         unsigned a0, unsigned a1, unsigned a2, unsigned a3,
                                         unsigned b0, unsigned b1) {
    asm volatile("mma.sync.aligned.m16n8k16.row.col.f32.bf16.bf16.f32 "
                 "{%0,%1,%2,%3}, {%4,%5,%6,%7}, {%8,%9}, {%0,%1,%2,%3};"
                 : "+f"(c0), "+f"(c1), "+f"(c2), "+f"(c3)
                 : "r"(a0), "r"(a1), "r"(a2), "r"(a3), "r"(b0), "r"(b1));
}

// ---------------- init ----------------
__global__ void k_init(float* var, int* assign, int* done, int* conflict) {
    int i = blockIdx.x * 256 + threadIdx.x;
    if (i < NVAR*Hh) var[i] = 0.f;
    if (i < NVAR) assign[i] = 2;
    if (i == 0) { *done = 0; *conflict = 0; }
}

// ---------------- split a [N x K] float matrix into bf16 planes (dim-pair packed) ----------------
__global__ void k_splitW(const float* __restrict__ W, unsigned* __restrict__ Wh,
                         unsigned* __restrict__ Wl) {
    int i = blockIdx.x * 256 + threadIdx.x;
    unsigned uh, ul;
    sp2(W[2*i], W[2*i+1], uh, ul);
    Wh[i] = uh; Wl[i] = ul;
}

// ---------------- split + transpose V: [(b,h)][dim 32][clause-pair 1024] ----------------
__global__ void k_splitVT(const float* __restrict__ Vb, unsigned* __restrict__ VhT,
                          unsigned* __restrict__ VlT) {
    int bh = blockIdx.x;          // 0..63
    int b = bh >> 3, h = bh & 7;
    int t = threadIdx.x;          // 256
    __shared__ float tile[64][33];
    for (int cc = 0; cc < Cc; cc += 64) {
        __syncthreads();
        #pragma unroll
        for (int rep = 0; rep < 8; rep++) {
            int idx = rep*256 + t;
            int cl = idx >> 5, d = idx & 31;
            tile[cl][d] = Vb[(long)(b*Cc + cc + cl)*Hh + h*32 + d];
        }
        __syncthreads();
        int d = t >> 3, j = t & 7;
        unsigned oh[4], ol[4];
        #pragma unroll
        for (int qq = 0; qq < 4; qq++) {
            int cp = j*4 + qq;
            sp2(tile[2*cp][d], tile[2*cp+1][d], oh[qq], ol[qq]);
        }
        long obase = ((long)(bh*32 + d) << 10) + (cc >> 1) + j*4;
        *(uint4*)(VhT + obase) = make_uint4(oh[0],oh[1],oh[2],oh[3]);
        *(uint4*)(VlT + obase) = make_uint4(ol[0],ol[1],ol[2],ol[3]);
    }
}

// ---------------- literal gather + mean over L ----------------
__global__ void k_mean(const int* __restrict__ formula, const float* __restrict__ lit_emb,
                       float* __restrict__ out) {
    int token = blockIdx.x;
    int d = threadIdx.x;
    int f0 = formula[token*3+0], f1 = formula[token*3+1], f2 = formula[token*3+2];
    float s = lit_emb[f0*Hh+d] + lit_emb[f1*Hh+d] + lit_emb[f2*Hh+d];
    out[(long)token*Hh + d] = s * (1.0f/3.0f);
}

// ---------------- LayerNorm (rows of 512) + gelu, in-place ----------------
__global__ void k_ln_gelu(float* __restrict__ x, const float* __restrict__ g,
                          const float* __restrict__ beta) {
    int row = blockIdx.x; int t = threadIdx.x;
    __shared__ float red[256];
    float a = x[(long)row*TWOH + t];
    float b_ = x[(long)row*TWOH + t + 256];
    red[t] = a + b_;
    __syncthreads();
    for (int s = 128; s; s >>= 1) { if (t < s) red[t] += red[t+s]; __syncthreads(); }
    float mean = red[0] * (1.0f/512.0f);
    __syncthreads();
    float da = a - mean, db = b_ - mean;
    red[t] = da*da + db*db;
    __syncthreads();
    for (int s = 128; s; s >>= 1) { if (t < s) red[t] += red[t+s]; __syncthreads(); }
    float var = red[0] * (1.0f/512.0f);
    float rstd = rsqrtf(var + 1e-5f);
    float ya = da * rstd * g[t]     + beta[t];
    float yb = db * rstd * g[t+256] + beta[t+256];
    x[(long)row*TWOH + t]       = gelu_f(ya);
    x[(long)row*TWOH + t + 256] = gelu_f(yb);
}

// ---------------- tensor-core 3-pass bf16 GEMM (float W, used by encoder) ----------------
__global__ void __launch_bounds__(128) k_gemm_tc(
        const float* __restrict__ A, const float* __restrict__ W,
        const float* __restrict__ bias, float* __restrict__ C,
        int M, int N, int K, int act) {
    __shared__ unsigned Ash[64][20], Asl[64][20];
    __shared__ unsigned Wsh[64][20], Wsl[64][20];
    int t = threadIdx.x, lane = t & 31, w = t >> 5;
    int gid = lane >> 2, tid = lane & 3;
    int m0 = blockIdx.y * 64, n0 = blockIdx.x * 64;
    float acc[8][4] = {};
    for (int k0 = 0; k0 < K; k0 += 32) {
        __syncthreads();
        #pragma unroll
        for (int rep = 0; rep < 4; rep++) {
            int idx = t + rep*128;
            int r = idx >> 3, c4 = (idx & 7) << 2;
            float4 av = *(const float4*)(A + (long)(m0+r)*K + k0 + c4);
            unsigned h0,l0,h1,l1;
            sp2(av.x, av.y, h0, l0); sp2(av.z, av.w, h1, l1);
            Ash[r][(c4>>1)] = h0; Ash[r][(c4>>1)+1] = h1;
            Asl[r][(c4>>1)] = l0; Asl[r][(c4>>1)+1] = l1;
            float4 wv = *(const float4*)(W + (long)(n0+r)*K + k0 + c4);
            sp2(wv.x, wv.y, h0, l0); sp2(wv.z, wv.w, h1, l1);
            Wsh[r][(c4>>1)] = h0; Wsh[r][(c4>>1)+1] = h1;
            Wsl[r][(c4>>1)] = l0; Wsl[r][(c4>>1)+1] = l1;
        }
        __syncthreads();
        #pragma unroll
        for (int kt = 0; kt < 2; kt++) {
            int ra = w*16 + gid, ku = kt*8 + tid;
            unsigned ah0 = Ash[ra  ][ku],  ah1 = Ash[ra+8][ku];
            unsigned ah2 = Ash[ra  ][ku+4], ah3 = Ash[ra+8][ku+4];
            unsigned al0 = Asl[ra  ][ku],  al1 = Asl[ra+8][ku];
            unsigned al2 = Asl[ra  ][ku+4], al3 = Asl[ra+8][ku+4];
            #pragma unroll
            for (int nt = 0; nt < 8; nt++) {
                int rb = nt*8 + gid;
                unsigned bh0 = Wsh[rb][ku], bh1 = Wsh[rb][ku+4];
                unsigned bl0 = Wsl[rb][ku], bl1 = Wsl[rb][ku+4];
                mma_bf16(acc[nt][0],acc[nt][1],acc[nt][2],acc[nt][3], ah0,ah1,ah2,ah3, bh0,bh1);
                mma_bf16(acc[nt][0],acc[nt][1],acc[nt][2],acc[nt][3], ah0,ah1,ah2,ah3, bl0,bl1);
                mma_bf16(acc[nt][0],acc[nt][1],acc[nt][2],acc[nt][3], al0,al1,al2,al3, bh0,bh1);
            }
        }
    }
    int r = m0 + w*16 + gid;
    #pragma unroll
    for (int nt = 0; nt < 8; nt++) {
        int c = n0 + nt*8 + 2*tid;
        float b0v = bias ? bias[c] : 0.0f;
        float b1v = bias ? bias[c+1] : 0.0f;
        float v0 = acc[nt][0] + b0v, v1 = acc[nt][1] + b1v;
        float v2 = acc[nt][2] + b0v, v3 = acc[nt][3] + b1v;
        if (act) { v0 = gelu_f(v0); v1 = gelu_f(v1); v2 = gelu_f(v2); v3 = gelu_f(v3); }
        *(float2*)(C + (long)r*N + c)     = make_float2(v0, v1);
        *(float2*)(C + (long)(r+8)*N + c) = make_float2(v2, v3);
    }
}

// ---------------- per-iter GEMM with PRE-SPLIT weights (float out, optional dup) ----------------
__global__ void __launch_bounds__(128) k_gemm_ps(
        const float* __restrict__ A,
        const unsigned* __restrict__ Wh, const unsigned* __restrict__ Wl,
        const float* __restrict__ bias, float* __restrict__ C,
        float* __restrict__ C2, int M, int N, int K, int act,
        const int* __restrict__ done) {
    if (*done) return;
    __shared__ unsigned Ash[64][20], Asl[64][20];
    __shared__ unsigned Wsh[64][20], Wsl[64][20];
    int t = threadIdx.x, lane = t & 31, w = t >> 5;
    int gid = lane >> 2, tid = lane & 3;
    int m0 = blockIdx.y * 64, n0 = blockIdx.x * 64;
    int Kh2 = K >> 1;
    float acc[8][4] = {};
    for (int k0 = 0; k0 < K; k0 += 32) {
        __syncthreads();
        #pragma unroll
        for (int rep = 0; rep < 4; rep++) {
            int idx = t + rep*128;
            int r = idx >> 3, c4 = (idx & 7) << 2;
            float4 av = *(const float4*)(A + (long)(m0+r)*K + k0 + c4);
            unsigned h0,l0,h1,l1;
            sp2(av.x, av.y, h0, l0); sp2(av.z, av.w, h1, l1);
            Ash[r][(c4>>1)] = h0; Ash[r][(c4>>1)+1] = h1;
            Asl[r][(c4>>1)] = l0; Asl[r][(c4>>1)+1] = l1;
        }
        #pragma unroll
        for (int rep = 0; rep < 2; rep++) {
            int idx4 = t + rep*128;
            int r = idx4 >> 2, u4 = (idx4 & 3) << 2;
            long gix = (long)(n0+r)*Kh2 + (k0>>1) + u4;
            *(uint4*)(&Wsh[r][u4]) = *(const uint4*)(Wh + gix);
            *(uint4*)(&Wsl[r][u4]) = *(const uint4*)(Wl + gix);
        }
        __syncthreads();
        #pragma unroll
        for (int kt = 0; kt < 2; kt++) {
            int ra = w*16 + gid, ku = kt*8 + tid;
            unsigned ah0 = Ash[ra  ][ku],  ah1 = Ash[ra+8][ku];
            unsigned ah2 = Ash[ra  ][ku+4], ah3 = Ash[ra+8][ku+4];
            unsigned al0 = Asl[ra  ][ku],  al1 = Asl[ra+8][ku];
            unsigned al2 = Asl[ra  ][ku+4], al3 = Asl[ra+8][ku+4];
            #pragma unroll
            for (int nt = 0; nt < 8; nt++) {
                int rb = nt*8 + gid;
                unsigned bh0 = Wsh[rb][ku], bh1 = Wsh[rb][ku+4];
                unsigned bl0 = Wsl[rb][ku], bl1 = Wsl[rb][ku+4];
                mma_bf16(acc[nt][0],acc[nt][1],acc[nt][2],acc[nt][3], ah0,ah1,ah2,ah3, bh0,bh1);
                mma_bf16(acc[nt][0],acc[nt][1],acc[nt][2],acc[nt][3], ah0,ah1,ah2,ah3, bl0,bl1);
                mma_bf16(acc[nt][0],acc[nt][1],acc[nt][2],acc[nt][3], al0,al1,al2,al3, bh0,bh1);
            }
        }
    }
    int r = m0 + w*16 + gid;
    #pragma unroll
    for (int nt = 0; nt < 8; nt++) {
        int c = n0 + nt*8 + 2*tid;
        float b0v = bias[c], b1v = bias[c+1];
        float v0 = acc[nt][0] + b0v, v1 = acc[nt][1] + b1v;
        float v2 = acc[nt][2] + b0v, v3 = acc[nt][3] + b1v;
        if (act) { v0 = gelu_f(v0); v1 = gelu_f(v1); v2 = gelu_f(v2); v3 = gelu_f(v3); }
        *(float2*)(C + (long)r*N + c)     = make_float2(v0, v1);
        *(float2*)(C + (long)(r+8)*N + c) = make_float2(v2, v3);
        if (C2) {
            *(float2*)(C2 + (long)r*N + c)     = make_float2(v0, v1);
            *(float2*)(C2 + (long)(r+8)*N + c) = make_float2(v2, v3);
        }
    }
}

// ---------------- Q GEMM: var @ Wq^T + bq -> split planes + per-head qb ----------------
__global__ void __launch_bounds__(128) k_gemm_q(
        const float* __restrict__ A,
        const unsigned* __restrict__ Wh, const unsigned* __restrict__ Wl,
        const float* __restrict__ attn_in_b,
        unsigned* __restrict__ Qh, unsigned* __restrict__ Ql,
        float* __restrict__ qb, const int* __restrict__ done) {
    if (*done) return;
    __shared__ unsigned Ash[64][20], Asl[64][20];
    __shared__ unsigned Wsh[64][20], Wsl[64][20];
    int t = threadIdx.x, lane = t & 31, w = t >> 5;
    int gid = lane >> 2, tid = lane & 3;
    int m0 = blockIdx.y * 64, n0 = blockIdx.x * 64;
    float acc[8][4] = {};
    for (int k0 = 0; k0 < Hh; k0 += 32) {
        __syncthreads();
        #pragma unroll
        for (int rep = 0; rep < 4; rep++) {
            int idx = t + rep*128;
            int r = idx >> 3, c4 = (idx & 7) << 2;
            float4 av = *(const float4*)(A + (long)(m0+r)*Hh + k0 + c4);
            unsigned h0,l0,h1,l1;
            sp2(av.x, av.y, h0, l0); sp2(av.z, av.w, h1, l1);
            Ash[r][(c4>>1)] = h0; Ash[r][(c4>>1)+1] = h1;
            Asl[r][(c4>>1)] = l0; Asl[r][(c4>>1)+1] = l1;
        }
        #pragma unroll
        for (int rep = 0; rep < 2; rep++) {
            int idx4 = t + rep*128;
            int r = idx4 >> 2, u4 = (idx4 & 3) << 2;
            long gix = (long)(n0+r)*128 + (k0>>1) + u4;
            *(uint4*)(&Wsh[r][u4]) = *(const uint4*)(Wh + gix);
            *(uint4*)(&Wsl[r][u4]) = *(const uint4*)(Wl + gix);
        }
        __syncthreads();
        #pragma unroll
        for (int kt = 0; kt < 2; kt++) {
            int ra = w*16 + gid, ku = kt*8 + tid;
            unsigned ah0 = Ash[ra  ][ku],  ah1 = Ash[ra+8][ku];
            unsigned ah2 = Ash[ra  ][ku+4], ah3 = Ash[ra+8][ku+4];
            unsigned al0 = Asl[ra  ][ku],  al1 = Asl[ra+8][ku];
            unsigned al2 = Asl[ra  ][ku+4], al3 = Asl[ra+8][ku+4];
            #pragma unroll
            for (int nt = 0; nt < 8; nt++) {
                int rb = nt*8 + gid;
                unsigned bh0 = Wsh[rb][ku], bh1 = Wsh[rb][ku+4];
                unsigned bl0 = Wsl[rb][ku], bl1 = Wsl[rb][ku+4];
                mma_bf16(acc[nt][0],acc[nt][1],acc[nt][2],acc[nt][3], ah0,ah1,ah2,ah3, bh0,bh1);
                mma_bf16(acc[nt][0],acc[nt][1],acc[nt][2],acc[nt][3], ah0,ah1,ah2,ah3, bl0,bl1);
                mma_bf16(acc[nt][0],acc[nt][1],acc[nt][2],acc[nt][3], al0,al1,al2,al3, bh0,bh1);
            }
        }
    }
    int r = m0 + w*16 + gid;
    const float* bq = attn_in_b + n0;
    const float* bk = attn_in_b + Hh + n0;
    float hs[4] = {0.f, 0.f, 0.f, 0.f};
    #pragma unroll
    for (int nt = 0; nt < 8; nt++) {
        int c = nt*8 + 2*tid;
        float b0 = bq[c], b1 = bq[c+1];
        float v0 = acc[nt][0] + b0, v1 = acc[nt][1] + b1;
        float v2 = acc[nt][2] + b0, v3 = acc[nt][3] + b1;
        float k0v = bk[c], k1v = bk[c+1];
        int hi = nt >> 2;
        hs[hi]   += v0*k0v + v1*k1v;
        hs[hi+2] += v2*k0v + v3*k1v;
        int cp = (n0 >> 1) + nt*4 + tid;
        unsigned uh, ul;
        sp2(v0, v1, uh, ul);
        Qh[(long)r*128 + cp] = uh; Ql[(long)r*128 + cp] = ul;
        sp2(v2, v3, uh, ul);
        Qh[(long)(r+8)*128 + cp] = uh; Ql[(long)(r+8)*128 + cp] = ul;
    }
    #pragma unroll
    for (int i = 0; i < 4; i++) {
        hs[i] += __shfl_xor_sync(0xffffffffu, hs[i], 1);
        hs[i] += __shfl_xor_sync(0xffffffffu, hs[i], 2);
    }
    if (tid == 0) {
        int hA = n0 >> 5;
        qb[r*8 + hA]     = hs[0];  qb[r*8 + hA + 1]     = hs[1];
        qb[(r+8)*8 + hA] = hs[2];  qb[(r+8)*8 + hA + 1] = hs[3];
    }
}

// ---------------- flash attention: 3-pass bf16, pre-split Q/K/V, fused clause-scale ----------------
#define BC 64
__global__ void __launch_bounds__(128) k_attn(
        const unsigned* __restrict__ Qhp, const unsigned* __restrict__ Qlp,
        const float* __restrict__ qbp,
        const unsigned* __restrict__ Kh, const unsigned* __restrict__ Kl,
        const unsigned* __restrict__ VhT, const unsigned* __restrict__ VlT,
        const int* __restrict__ formula, const int* __restrict__ assign,
        const float* __restrict__ attn_in_b, float* __restrict__ out,
        const int* __restrict__ done) {
    if (*done) return;
    int bid = blockIdx.x;
    int qt = bid & 7;
    int h  = (bid >> 3) & 7;
    int b  = bid >> 6;
    int t = threadIdx.x, lane = t & 31, w = t >> 5;
    int gid = lane >> 2, tid = lane & 3;

    __shared__ unsigned Ksh[BC][20], Ksl[BC][20];
    __shared__ unsigned Vsh[HD][36], Vsl[HD][36];
    __shared__ float    scs[BC];

    int row0 = qt * 64;
    int rA = b*Vv + row0 + w*16 + gid;
    unsigned qh[2][4], ql[2][4];
    {
        long q0 = ((long)rA << 7) + h*16;
        long q1 = q0 + (8 << 7);
        #pragma unroll
        for (int kt = 0; kt < 2; kt++) {
            int u = kt*8 + tid;
            qh[kt][0] = Qhp[q0 + u];     qh[kt][1] = Qhp[q1 + u];
            qh[kt][2] = Qhp[q0 + u + 4]; qh[kt][3] = Qhp[q1 + u + 4];
            ql[kt][0] = Qlp[q0 + u];     ql[kt][1] = Qlp[q1 + u];
            ql[kt][2] = Qlp[q0 + u + 4]; ql[kt][3] = Qlp[q1 + u + 4];
        }
    }
    float qb0 = qbp[rA*8 + h];
    float qb1 = qbp[(rA+8)*8 + h];

    float m0 = -1e30f, m1 = -1e30f, s0a = 0.f, s1a = 0.f;
    float o_[4][4] = {};
    const float inv = 0.17677669529663688110f;   // 1/sqrt(32)
    long vbase = ((long)((b*8 + h)*HD) << 10);

    for (int c0 = 0; c0 < Cc; c0 += BC) {
        __syncthreads();
        if (t < BC) {
            int cg = b*Cc + c0 + t;
            int f0 = formula[cg*3+0], f1 = formula[cg*3+1], f2 = formula[cg*3+2];
            int a0 = assign[b*Vv + (f0>>1)];
            int a1 = assign[b*Vv + (f1>>1)];
            int a2 = assign[b*Vv + (f2>>1)];
            bool sat = (a0 == (f0&1)) || (a1 == (f1&1)) || (a2 == (f2&1));
            scs[t] = sat ? 0.1f : 1.0f;
        }
        #pragma unroll
        for (int rep = 0; rep < 2; rep++) {
            int idx4 = t + rep*128;
            int c = idx4 >> 2, u4 = (idx4 & 3) << 2;
            long gix = ((long)(b*Cc + c0 + c) << 7) + (h << 4) + u4;
            *(uint4*)(&Ksh[c][u4]) = *(const uint4*)(Kh + gix);
            *(uint4*)(&Ksl[c][u4]) = *(const uint4*)(Kl + gix);
        }
        #pragma unroll
        for (int rep = 0; rep < 2; rep++) {
            int idx4 = t + rep*128;
            int d = idx4 >> 3, j4 = (idx4 & 7) << 2;
            long gix = vbase + ((long)d << 10) + (c0 >> 1) + j4;
            *(uint4*)(&Vsh[d][j4]) = *(const uint4*)(VhT + gix);
            *(uint4*)(&Vsl[d][j4]) = *(const uint4*)(VlT + gix);
        }
        __syncthreads();

        float sc_[8][4];
        #pragma unroll
        for (int nt = 0; nt < 8; nt++) {
            float a0 = 0.f, a1 = 0.f, a2 = 0.f, a3 = 0.f;
            #pragma unroll
            for (int kt = 0; kt < 2; kt++) {
                int cn = nt*8 + gid, ku = kt*8 + tid;
                unsigned bh0 = Ksh[cn][ku], bh1 = Ksh[cn][ku+4];
                unsigned bl0 = Ksl[cn][ku], bl1 = Ksl[cn][ku+4];
                mma_bf16(a0,a1,a2,a3, qh[kt][0],qh[kt][1],qh[kt][2],qh[kt][3], bh0,bh1);
                mma_bf16(a0,a1,a2,a3, qh[kt][0],qh[kt][1],qh[kt][2],qh[kt][3], bl0,bl1);
                mma_bf16(a0,a1,a2,a3, ql[kt][0],ql[kt][1],ql[kt][2],ql[kt][3], bh0,bh1);
            }
            sc_[nt][0]=a0; sc_[nt][1]=a1; sc_[nt][2]=a2; sc_[nt][3]=a3;
        }

        float rm0 = -1e30f, rm1 = -1e30f;
        #pragma unroll
        for (int nt = 0; nt < 8; nt++) {
            float scA = scs[nt*8 + 2*tid];
            float scB = scs[nt*8 + 2*tid + 1];
            sc_[nt][0] = fmaf(sc_[nt][0], scA, qb0) * inv;
            sc_[nt][1] = fmaf(sc_[nt][1], scB, qb0) * inv;
            sc_[nt][2] = fmaf(sc_[nt][2], scA, qb1) * inv;
            sc_[nt][3] = fmaf(sc_[nt][3], scB, qb1) * inv;
            rm0 = fmaxf(rm0, fmaxf(sc_[nt][0], sc_[nt][1]));
            rm1 = fmaxf(rm1, fmaxf(sc_[nt][2], sc_[nt][3]));
        }
        rm0 = fmaxf(rm0, __shfl_xor_sync(0xffffffffu, rm0, 1));
        rm0 = fmaxf(rm0, __shfl_xor_sync(0xffffffffu, rm0, 2));
        rm1 = fmaxf(rm1, __shfl_xor_sync(0xffffffffu, rm1, 1));
        rm1 = fmaxf(rm1, __shfl_xor_sync(0xffffffffu, rm1, 2));
        float mn0 = fmaxf(m0, rm0), mn1 = fmaxf(m1, rm1);
        float corr0 = __expf(m0 - mn0), corr1 = __expf(m1 - mn1);
        float ps0 = 0.f, ps1 = 0.f;
        #pragma unroll
        for (int nt = 0; nt < 8; nt++) {
            sc_[nt][0] = __expf(sc_[nt][0] - mn0);
            sc_[nt][1] = __expf(sc_[nt][1] - mn0);
            sc_[nt][2] = __expf(sc_[nt][2] - mn1);
            sc_[nt][3] = __expf(sc_[nt][3] - mn1);
            ps0 += sc_[nt][0] + sc_[nt][1];
            ps1 += sc_[nt][2] + sc_[nt][3];
        }
        ps0 += __shfl_xor_sync(0xffffffffu, ps0, 1);
        ps0 += __shfl_xor_sync(0xffffffffu, ps0, 2);
        ps1 += __shfl_xor_sync(0xffffffffu, ps1, 1);
        ps1 += __shfl_xor_sync(0xffffffffu, ps1, 2);
        s0a = s0a*corr0 + ps0;
        s1a = s1a*corr1 + ps1;
        m0 = mn0; m1 = mn1;

        #pragma unroll
        for (int nt2 = 0; nt2 < 4; nt2++) {
            o_[nt2][0] *= corr0; o_[nt2][1] *= corr0;
            o_[nt2][2] *= corr1; o_[nt2][3] *= corr1;
        }

        #pragma unroll
        for (int kt = 0; kt < 4; kt++) {
            int cA = kt*16 + 2*tid;
            float sA = scs[cA], sB = scs[cA+1], sC = scs[cA+8], sD = scs[cA+9];
            unsigned ah0, al0, ah1, al1, ah2, al2, ah3, al3;
            sp2(sc_[2*kt  ][0]*sA, sc_[2*kt  ][1]*sB, ah0, al0);
            sp2(sc_[2*kt  ][2]*sA, sc_[2*kt  ][3]*sB, ah1, al1);
            sp2(sc_[2*kt+1][0]*sC, sc_[2*kt+1][1]*sD, ah2, al2);
            sp2(sc_[2*kt+1][2]*sC, sc_[2*kt+1][3]*sD, ah3, al3);
            #pragma unroll
            for (int nt2 = 0; nt2 < 4; nt2++) {
                int d = nt2*8 + gid, ku = kt*8 + tid;
                unsigned bh0 = Vsh[d][ku], bh1 = Vsh[d][ku+4];
                unsigned bl0 = Vsl[d][ku], bl1 = Vsl[d][ku+4];
                mma_bf16(o_[nt2][0],o_[nt2][1],o_[nt2][2],o_[nt2][3], ah0,ah1,ah2,ah3, bh0,bh1);
                mma_bf16(o_[nt2][0],o_[nt2][1],o_[nt2][2],o_[nt2][3], ah0,ah1,ah2,ah3, bl0,bl1);
                mma_bf16(o_[nt2][0],o_[nt2][1],o_[nt2][2],o_[nt2][3], al0,al1,al2,al3, bh0,bh1);
            }
        }
    }

    const float* bvp = attn_in_b + 2*Hh + h*HD;
    float is0 = 1.0f / s0a, is1 = 1.0f / s1a;
    #pragma unroll
    for (int nt2 = 0; nt2 < 4; nt2++) {
        int d = nt2*8 + 2*tid;
        float2 bvv = *(const float2*)(bvp + d);
        float2 w0 = make_float2(o_[nt2][0]*is0 + bvv.x, o_[nt2][1]*is0 + bvv.y);
        float2 w1v = make_float2(o_[nt2][2]*is1 + bvv.x, o_[nt2][3]*is1 + bvv.y);
        *(float2*)(out + ((long)rA << 8) + (h << 5) + d) = w0;
        *(float2*)(out + ((long)(rA + 8) << 8) + (h << 5) + d) = w1v;
    }
}

// ---------------- score head (parallel: NVAR/8 blocks) ----------------
__global__ void k_scores(const float* __restrict__ h1, const float* __restrict__ w2,
                         const float* __restrict__ b2, const int* __restrict__ assign,
                         float* __restrict__ scores, const int* __restrict__ done) {
    if (*done) return;
    int row = blockIdx.x * 8 + (threadIdx.x >> 5);
    int lane = threadIdx.x & 31;
    const float* hr = h1 + (long)row * Hh;
    float acc = 0.f;
    #pragma unroll
    for (int i = 0; i < 8; i++) acc = fmaf(hr[lane + 32*i], w2[lane + 32*i], acc);
    #pragma unroll
    for (int o = 16; o; o >>= 1) acc += __shfl_xor_sync(0xffffffffu, acc, o);
    if (lane == 0) {
        float sc = acc + b2[0];
        if (assign[row] != 2) sc += -1000000000.0f;
        scores[row] = sc;
    }
}

// ---------------- select + ap head + assign update + conflict (fused) ----------------
__global__ void k_select(const float* __restrict__ vs, const float* __restrict__ scores,
                         int* __restrict__ assign,
                         const float* __restrict__ w1, const float* __restrict__ b1,
                         const float* __restrict__ w2, const float* __restrict__ b2,
                         const int* __restrict__ formula,
                         int* __restrict__ sel_out, const int* __restrict__ done,
                         int* __restrict__ conflict) {
    int b = blockIdx.x, t = threadIdx.x;
    if (*done) return;
    __shared__ float sv[256];
    __shared__ int   si[256];
    __shared__ float vsel[256];
    __shared__ float hbuf[256];
    __shared__ float r0s[256];
    __shared__ float r1s[256];
    float v1 = scores[b*Vv + t], v2 = scores[b*Vv + t + 256];
    float bvv; int bi;
    if (v2 > v1) { bvv = v2; bi = t + 256; } else { bvv = v1; bi = t; }
    sv[t] = bvv; si[t] = bi;
    __syncthreads();
    for (int s = 128; s; s >>= 1) {
        if (t < s) {
            if (sv[t+s] > sv[t] || (sv[t+s] == sv[t] && si[t+s] < si[t])) {
                sv[t] = sv[t+s]; si[t] = si[t+s];
            }
        }
        __syncthreads();
    }
    int sel = si[0];
    vsel[t] = vs[((long)(b*Vv + sel)) * Hh + t];
    __syncthreads();
    int w = t >> 5, lane = t & 31;
    for (int oo = 0; oo < 32; oo++) {
        int o = w*32 + oo;
        float acc = 0.f;
        #pragma unroll
        for (int kk = 0; kk < 8; kk++)
            acc = fmaf(w1[o*Hh + lane + 32*kk], vsel[lane + 32*kk], acc);
        #pragma unroll
        for (int off = 16; off; off >>= 1) acc += __shfl_xor_sync(0xffffffffu, acc, off);
        if (lane == 0) hbuf[o] = gelu_f(acc + b1[o]);
    }
    __syncthreads();
    float hv = hbuf[t];
    r0s[t] = hv * w2[t];
    r1s[t] = hv * w2[Hh + t];
    __syncthreads();
    for (int s = 128; s; s >>= 1) {
        if (t < s) { r0s[t] += r0s[t+s]; r1s[t] += r1s[t+s]; }
        __syncthreads();
    }
    if (t == 0) {
        float l0 = r0s[0] + b2[0], l1 = r1s[0] + b2[1];
        assign[b*Vv + sel] = (l1 > l0) ? 1 : 0;
        sel_out[b] = sel;
    }
    __syncthreads();
    // conflict detection on own batch (post-update)
    int myconf = 0;
    for (int i = t; i < Cc; i += 256) {
        int cg = b*Cc + i;
        int f0 = formula[cg*3+0], f1 = formula[cg*3+1], f2 = formula[cg*3+2];
        int a0 = assign[b*Vv + (f0>>1)];
        int a1 = assign[b*Vv + (f1>>1)];
        int a2 = assign[b*Vv + (f2>>1)];
        bool sat = (a0 == (f0&1)) || (a1 == (f1&1)) || (a2 == (f2&1));
        bool allass = (a0 != 2) && (a1 != 2) && (a2 != 2);
        if (allass && !sat) myconf = 1;
    }
    if (__syncthreads_or(myconf)) {
        if (t == 0) atomicOr(conflict, 1);
    }
}

// ---------------- rollback + done update (resets conflict for next iter) ----------------
__global__ void k_finalize(int* __restrict__ assign, const int* __restrict__ sel,
                           int* __restrict__ done, int* __restrict__ conflict) {
    __shared__ int red[256];
    __shared__ int sconf;
    int t = threadIdx.x;
    if (*done) return;
    if (t == 0) { sconf = *conflict; *conflict = 0; }
    __syncthreads();
    int conf = sconf;
    if (conf && t < Bb) assign[t*Vv + sel[t]] = 2;
    __syncthreads();
    int ok = 1;
    for (int i = t; i < NVAR; i += 256) ok &= (assign[i] != 2) ? 1 : 0;
    red[t] = ok;
    __syncthreads();
    for (int s = 128; s; s >>= 1) { if (t < s) red[t] &= red[t+s]; __syncthreads(); }
    if (t == 0 && red[0] && !conf) *done = 1;
}

// ---------------- final sat-probability head ----------------
__global__ void k_satout(const float* __restrict__ var,
                         const float* __restrict__ w1, const float* __restrict__ b1,
                         const float* __restrict__ w2, const float* __restrict__ b2,
                         float* __restrict__ out) {
    int b = blockIdx.x, t = threadIdx.x;
    __shared__ float msh[256];
    __shared__ float hbuf[256];
    __shared__ float red[256];
    float ssum_ = 0.f;
    for (int v = 0; v < Vv; v++) ssum_ += var[((long)(b*Vv + v)) * Hh + t];
    msh[t] = ssum_ * (1.0f/512.0f);
    __syncthreads();
    int w = t >> 5, lane = t & 31;
    for (int oo = 0; oo < 32; oo++) {
        int o = w*32 + oo;
        float acc = 0.f;
        #pragma unroll
        for (int kk = 0; kk < 8; kk++)
            acc = fmaf(w1[o*Hh + lane + 32*kk], msh[lane + 32*kk], acc);
        #pragma unroll
        for (int off = 16; off; off >>= 1) acc += __shfl_xor_sync(0xffffffffu, acc, off);
        if (lane == 0) hbuf[o] = gelu_f(acc + b1[o]);
    }
    __syncthreads();
    red[t] = hbuf[t] * w2[t];
    __syncthreads();
    for (int s = 128; s; s >>= 1) { if (t < s) red[t] += red[t+s]; __syncthreads(); }
    if (t == 0) {
        float l = red[0] + b2[0];
        out[b] = 1.0f / (1.0f + expf(-l));
    }
}

__global__ void k_assignout(const int* __restrict__ assign, float* __restrict__ out) {
    int i = blockIdx.x * 256 + threadIdx.x;
    if (i < NVAR) out[Bb + i] = (float)assign[i];
}

// ---------------- host launch ----------------
extern "C" void kernel_launch(void* const* d_in, const int* in_sizes, int n_in,
                              void* d_out, int out_size) {
    const int*   formula    = (const int*)  d_in[0];
    const float* lit_emb    = (const float*)d_in[1];
    const float* ce_w1      = (const float*)d_in[2];
    const float* ce_b1      = (const float*)d_in[3];
    const float* ce_g       = (const float*)d_in[4];
    const float* ce_beta    = (const float*)d_in[5];
    const float* ce_w2      = (const float*)d_in[6];
    const float* ce_b2      = (const float*)d_in[7];
    const float* attn_in_w  = (const float*)d_in[8];
    const float* attn_in_b  = (const float*)d_in[9];
    const float* attn_out_w = (const float*)d_in[10];
    const float* attn_out_b = (const float*)d_in[11];
    const float* vs_w1      = (const float*)d_in[12];
    const float* vs_b1      = (const float*)d_in[13];
    const float* vs_w2      = (const float*)d_in[14];
    const float* vs_b2      = (const float*)d_in[15];
    const float* ap_w1      = (const float*)d_in[16];
    const float* ap_b1      = (const float*)d_in[17];
    const float* ap_w2      = (const float*)d_in[18];
    const float* ap_b2      = (const float*)d_in[19];
    const float* sp_w1      = (const float*)d_in[20];
    const float* sp_b1      = (const float*)d_in[21];
    const float* sp_w2      = (const float*)d_in[22];
    const float* sp_b2      = (const float*)d_in[23];
    float* out = (float*)d_out;

    float *p_mean, *p_x1, *p_base, *p_Kb, *p_Vb, *p_var, *p_attno, *p_vs, *p_h1, *p_qb, *p_scores;
    unsigned *p_Kh, *p_Kl, *p_VhT, *p_VlT, *p_Qh, *p_Ql;
    unsigned *p_Wqh, *p_Wql, *p_Woh, *p_Wol, *p_Wv1h, *p_Wv1l;
    int *p_assign, *p_sel, *p_conf, *p_done;
    cudaGetSymbolAddress((void**)&p_mean,  g_mean);
    cudaGetSymbolAddress((void**)&p_x1,    g_x1);
    cudaGetSymbolAddress((void**)&p_base,  g_base);
    cudaGetSymbolAddress((void**)&p_Kb,    g_Kb);
    cudaGetSymbolAddress((void**)&p_Vb,    g_Vb);
    cudaGetSymbolAddress((void**)&p_Kh,    g_Kh);
    cudaGetSymbolAddress((void**)&p_Kl,    g_Kl);
    cudaGetSymbolAddress((void**)&p_VhT,   g_VhT);
    cudaGetSymbolAddress((void**)&p_VlT,   g_VlT);
    cudaGetSymbolAddress((void**)&p_Qh,    g_Qh);
    cudaGetSymbolAddress((void**)&p_Ql,    g_Ql);
    cudaGetSymbolAddress((void**)&p_qb,    g_qb);
    cudaGetSymbolAddress((void**)&p_Wqh,   g_Wqh);
    cudaGetSymbolAddress((void**)&p_Wql,   g_Wql);
    cudaGetSymbolAddress((void**)&p_Woh,   g_Woh);
    cudaGetSymbolAddress((void**)&p_Wol,   g_Wol);
    cudaGetSymbolAddress((void**)&p_Wv1h,  g_Wv1h);
    cudaGetSymbolAddress((void**)&p_Wv1l,  g_Wv1l);
    cudaGetSymbolAddress((void**)&p_var,   g_var);
    cudaGetSymbolAddress((void**)&p_attno, g_attno);
    cudaGetSymbolAddress((void**)&p_vs,    g_vs);
    cudaGetSymbolAddress((void**)&p_h1,    g_h1);
    cudaGetSymbolAddress((void**)&p_scores,g_scores);
    cudaGetSymbolAddress((void**)&p_assign,g_assign);
    cudaGetSymbolAddress((void**)&p_sel,   g_sel);
    cudaGetSymbolAddress((void**)&p_conf,  g_conflict);
    cudaGetSymbolAddress((void**)&p_done,  g_done);

    // init state
    k_init<<<(NVAR*Hh + 255)/256, 256>>>(p_var, p_assign, p_done, p_conf);

    // pre-split loop-invariant weights
    k_splitW<<<Hh*128/256, 256>>>(attn_in_w,  p_Wqh,  p_Wql);
    k_splitW<<<Hh*128/256, 256>>>(attn_out_w, p_Woh,  p_Wol);
    k_splitW<<<Hh*128/256, 256>>>(vs_w1,      p_Wv1h, p_Wv1l);

    // clause encoder (once)
    k_mean<<<NTOK, 256>>>(formula, lit_emb, p_mean);
    k_gemm_tc<<<dim3(TWOH/64, NTOK/64), 128>>>(p_mean, ce_w1, ce_b1, p_x1, NTOK, TWOH, Hh, 0);
    k_ln_gelu<<<NTOK, 256>>>(p_x1, ce_g, ce_beta);
    k_gemm_tc<<<dim3(Hh/64, NTOK/64), 128>>>(p_x1, ce_w2, ce_b2, p_base, NTOK, Hh, TWOH, 0);
    k_gemm_tc<<<dim3(Hh/64, NTOK/64), 128>>>(p_base, attn_in_w + Hh*Hh,   nullptr, p_Kb, NTOK, Hh, Hh, 0);
    k_gemm_tc<<<dim3(Hh/64, NTOK/64), 128>>>(p_base, attn_in_w + 2*Hh*Hh, nullptr, p_Vb, NTOK, Hh, Hh, 0);
    k_splitW<<<NTOK*128/256, 256>>>(p_Kb, p_Kh, p_Kl);
    k_splitVT<<<64, 256>>>(p_Vb, p_VhT, p_VlT);

    for (int it = 0; it < ITERS; it++) {
        k_gemm_q<<<dim3(4, NVAR/64), 128>>>(p_var, p_Wqh, p_Wql, attn_in_b,
                                            p_Qh, p_Ql, p_qb, p_done);
        k_attn<<<Bb*HEADS*(Vv/64), 128>>>(p_Qh, p_Ql, p_qb, p_Kh, p_Kl, p_VhT, p_VlT,
                                          formula, p_assign, attn_in_b, p_attno, p_done);
        // attn-out projection; fused commit: var = vs (both gated on done)
        k_gemm_ps<<<dim3(Hh/64, NVAR/64), 128>>>(p_attno, p_Woh, p_Wol, attn_out_b,
                                                 p_vs, p_var, NVAR, Hh, Hh, 0, p_done);
        k_gemm_ps<<<dim3(Hh/64, NVAR/64), 128>>>(p_vs, p_Wv1h, p_Wv1l, vs_b1,
                                                 p_h1, nullptr, NVAR, Hh, Hh, 1, p_done);
        k_scores<<<NVAR/8, 256>>>(p_h1, vs_w2, vs_b2, p_assign, p_scores, p_done);
        k_select<<<Bb, 256>>>(p_vs, p_scores, p_assign, ap_w1, ap_b1, ap_w2, ap_b2,
                              formula, p_sel, p_done, p_conf);
        k_finalize<<<1, 256>>>(p_assign, p_sel, p_done, p_conf);
    }

    k_satout<<<Bb, 256>>>(p_var, sp_w1, sp_b1, sp_w2, sp_b2, out);
    k_assignout<<<NVAR/256, 256>>>(p_assign, out);

    (void)in_sizes; (void)n_in; (void)out_size;
}